// round 11
// baseline (speedup 1.0000x reference)
#include <cuda_runtime.h>
#include <cuda_bf16.h>
#include <math.h>
#include <stdint.h>

// Problem constants
#define B_   16
#define T_   2048
#define E_   1024
#define H_   64

// Scratch for q,k,v projections (device globals: no allocation allowed)
__device__ float g_q[B_ * T_ * H_];
__device__ float g_k[B_ * T_ * H_];
__device__ float g_v[B_ * T_ * H_];

// Attention split-K partials: per (b, qi, chunk): O[64][64] + m[64] + l[64]
#define PART_STRIDE (64 * 64 + 64 + 64)            // 4224 floats
__device__ float g_part[(size_t)B_ * 32 * 4 * PART_STRIDE];   // 34.6 MB

// ---------------------------------------------------------------------------
// helpers: tf32 convert + warp MMA m16n8k8 (tf32 inputs, fp32 accum)
// ---------------------------------------------------------------------------
__device__ __forceinline__ uint32_t f2t(float x) {
    uint32_t r;
    asm("cvt.rna.tf32.f32 %0, %1;" : "=r"(r) : "f"(x));
    return r;
}

__device__ __forceinline__ void mma_tf32(float c[4],
                                         uint32_t a0, uint32_t a1, uint32_t a2, uint32_t a3,
                                         uint32_t b0, uint32_t b1)
{
    asm volatile(
        "mma.sync.aligned.m16n8k8.row.col.f32.tf32.tf32.f32 "
        "{%0,%1,%2,%3}, {%4,%5,%6,%7}, {%8,%9}, {%0,%1,%2,%3};\n"
        : "+f"(c[0]), "+f"(c[1]), "+f"(c[2]), "+f"(c[3])
        : "r"(a0), "r"(a1), "r"(a2), "r"(a3), "r"(b0), "r"(b1));
}

// ---------------------------------------------------------------------------
// Kernel 1: FUSED QKV projection via 3xTF32 MMA, register-prefetch pipeline.
// [k|q|v] = x @ [Wk|Wq|Wv].  Block: 256 threads (8 warps).
// M-tile 64, N = 192 (3 x 64), K chunks of 32.
// Warp w: rows (w&3)*16..+16, nt block (w>>2)*12..+12.
// Next chunk's LDGs issue before the MMA phase -> latency hidden.
// smem strides: xs 36 (==4 mod 32), ws 200 (==8 mod 32): frag-conflict-free.
// ---------------------------------------------------------------------------
#define XS_S 36
#define WS_S 200
#define PROJ_SMEM ((64*XS_S*2 + 32*WS_S*2) * 4)   // 69632 B

__global__ __launch_bounds__(256) void proj_kernel(
    const float* __restrict__ x,
    const float* __restrict__ Wk,
    const float* __restrict__ Wq,
    const float* __restrict__ Wv)
{
    extern __shared__ uint32_t psm[];
    uint32_t* xh = psm;                    // 64*36
    uint32_t* xl = xh + 64 * XS_S;
    uint32_t* wh = xl + 64 * XS_S;         // 32*200
    uint32_t* wl = wh + 32 * WS_S;

    const int tid  = threadIdx.x;
    const int w    = tid >> 5;
    const int lane = tid & 31;
    const int g    = lane >> 2;
    const int t    = lane & 3;
    const int mw   = w & 3;                // row block 0..3
    const int nh   = w >> 2;               // n half 0/1
    const long rowBase = (long)blockIdx.x * 64;

    float acc[12][4] = {};
    float4 px[2], pw[6];

    // prefetch chunk 0
    #pragma unroll
    for (int i = 0; i < 2; i++) {
        int idx = tid + i * 256;
        int r = idx >> 3, c = (idx & 7) * 4;
        px[i] = *(const float4*)&x[(rowBase + r) * E_ + c];
    }
    #pragma unroll
    for (int i = 0; i < 6; i++) {
        int idx = tid + i * 256;
        int r = idx / 48, c = (idx % 48) * 4;
        const float* Wsel = (c < 64) ? Wk : ((c < 128) ? Wq : Wv);
        pw[i] = *(const float4*)&Wsel[(long)r * H_ + (c & 63)];
    }

    for (int k0 = 0; k0 < E_; k0 += 32) {
        __syncthreads();   // previous MMA phase done reading smem
        // convert + store staged chunk
        #pragma unroll
        for (int i = 0; i < 2; i++) {
            int idx = tid + i * 256;
            int r = idx >> 3, c = (idx & 7) * 4;
            float4 v = px[i];
            float hx = __uint_as_float(f2t(v.x));
            float hy = __uint_as_float(f2t(v.y));
            float hz = __uint_as_float(f2t(v.z));
            float hw = __uint_as_float(f2t(v.w));
            *(uint4*)&xh[r * XS_S + c] =
                make_uint4(__float_as_uint(hx), __float_as_uint(hy),
                           __float_as_uint(hz), __float_as_uint(hw));
            *(uint4*)&xl[r * XS_S + c] =
                make_uint4(f2t(v.x - hx), f2t(v.y - hy),
                           f2t(v.z - hz), f2t(v.w - hw));
        }
        #pragma unroll
        for (int i = 0; i < 6; i++) {
            int idx = tid + i * 256;
            int r = idx / 48, c = (idx % 48) * 4;
            float4 v = pw[i];
            float hx = __uint_as_float(f2t(v.x));
            float hy = __uint_as_float(f2t(v.y));
            float hz = __uint_as_float(f2t(v.z));
            float hw = __uint_as_float(f2t(v.w));
            *(uint4*)&wh[r * WS_S + c] =
                make_uint4(__float_as_uint(hx), __float_as_uint(hy),
                           __float_as_uint(hz), __float_as_uint(hw));
            *(uint4*)&wl[r * WS_S + c] =
                make_uint4(f2t(v.x - hx), f2t(v.y - hy),
                           f2t(v.z - hz), f2t(v.w - hw));
        }
        __syncthreads();   // smem chunk visible

        // prefetch next chunk (overlaps with MMA below)
        if (k0 + 32 < E_) {
            const int kn = k0 + 32;
            #pragma unroll
            for (int i = 0; i < 2; i++) {
                int idx = tid + i * 256;
                int r = idx >> 3, c = (idx & 7) * 4;
                px[i] = *(const float4*)&x[(rowBase + r) * E_ + kn + c];
            }
            #pragma unroll
            for (int i = 0; i < 6; i++) {
                int idx = tid + i * 256;
                int r = idx / 48, c = (idx % 48) * 4;
                const float* Wsel = (c < 64) ? Wk : ((c < 128) ? Wq : Wv);
                pw[i] = *(const float4*)&Wsel[(long)(kn + r) * H_ + (c & 63)];
            }
        }

        // MMA phase
        #pragma unroll
        for (int ks8 = 0; ks8 < 4; ks8++) {
            const int kk = ks8 * 8;
            const int r0 = mw * 16 + g;
            uint32_t ah0 = xh[(r0    ) * XS_S + kk + t];
            uint32_t ah1 = xh[(r0 + 8) * XS_S + kk + t];
            uint32_t ah2 = xh[(r0    ) * XS_S + kk + t + 4];
            uint32_t ah3 = xh[(r0 + 8) * XS_S + kk + t + 4];
            uint32_t al0 = xl[(r0    ) * XS_S + kk + t];
            uint32_t al1 = xl[(r0 + 8) * XS_S + kk + t];
            uint32_t al2 = xl[(r0    ) * XS_S + kk + t + 4];
            uint32_t al3 = xl[(r0 + 8) * XS_S + kk + t + 4];
            #pragma unroll
            for (int ntl = 0; ntl < 12; ntl++) {
                const int nt = nh * 12 + ntl;
                uint32_t bh0 = wh[(kk + t    ) * WS_S + nt * 8 + g];
                uint32_t bh1 = wh[(kk + t + 4) * WS_S + nt * 8 + g];
                uint32_t bl0 = wl[(kk + t    ) * WS_S + nt * 8 + g];
                uint32_t bl1 = wl[(kk + t + 4) * WS_S + nt * 8 + g];
                mma_tf32(acc[ntl], ah0, ah1, ah2, ah3, bh0, bh1);
                mma_tf32(acc[ntl], al0, al1, al2, al3, bh0, bh1);
                mma_tf32(acc[ntl], ah0, ah1, ah2, ah3, bl0, bl1);
            }
        }
    }

    // store: ntg 0..7 -> g_k, 8..15 -> g_q, 16..23 -> g_v
    const long r0 = rowBase + mw * 16 + g;
    #pragma unroll
    for (int ntl = 0; ntl < 12; ntl++) {
        const int ntg = nh * 12 + ntl;
        float* o = (ntg < 8) ? g_k : ((ntg < 16) ? g_q : g_v);
        int c = (ntg & 7) * 8 + 2 * t;
        *(float2*)&o[(r0    ) * H_ + c] = make_float2(acc[ntl][0], acc[ntl][1]);
        *(float2*)&o[(r0 + 8) * H_ + c] = make_float2(acc[ntl][2], acc[ntl][3]);
    }
}

// ---------------------------------------------------------------------------
// Kernel 2: causal flash attention partials, tf32 MMA, split-K chunks.
// Block: 128 threads (4 warps). Q-tile 64 x K-tile 64.
// Work item = (qi, chunk c): key tiles j in [c*8, min(c*8+7, qi)].
// Writes UNNORMALIZED O + (m, l) per row to g_part[(b,qi,c)].
// blockIdx.x (0..79) decodes to (qi desc, c asc) so big chunks launch first.
// ---------------------------------------------------------------------------
#define QS_S 68
#define KS_S 68
#define VS_S 72
#define PS_S 68
#define ATTN_SMEM ((64*QS_S + 64*KS_S + 64*VS_S + 64*PS_S) * 4)  // 70656 B

__global__ __launch_bounds__(128) void attn_kernel()
{
    extern __shared__ uint32_t asm_[];
    uint32_t* qs = asm_;
    uint32_t* ks = qs + 64 * QS_S;
    uint32_t* vs = ks + 64 * KS_S;
    uint32_t* ps = vs + 64 * VS_S;

    // decode work item: qi from 31 down, chunks within
    int widx = blockIdx.x;
    int qi = 31, c = 0;
    for (;; qi--) {
        int nch = (qi >> 3) + 1;
        if (widx < nch) { c = widx; break; }
        widx -= nch;
    }
    const int b = blockIdx.y;
    const int jstart = c * 8;
    const int jend   = min(jstart + 7, qi);

    const int tid  = threadIdx.x;
    const int w    = tid >> 5;
    const int lane = tid & 31;
    const int g    = lane >> 2;
    const int t    = lane & 3;

    const float* qb = g_q + ((long)b * T_ + (long)qi * 64) * H_;
    const float* kb = g_k + (long)b * T_ * H_;
    const float* vb = g_v + (long)b * T_ * H_;

    // load Q tile -> tf32 smem (1024 float4: 128 thr x 8)
    #pragma unroll
    for (int i = 0; i < 8; i++) {
        int idx = tid + i * 128;
        int r = idx >> 4, cc = (idx & 15) * 4;
        float4 v = *(const float4*)&qb[r * H_ + cc];
        *(uint4*)&qs[r * QS_S + cc] =
            make_uint4(f2t(v.x), f2t(v.y), f2t(v.z), f2t(v.w));
    }

    float oc[8][4] = {};
    float m0 = -INFINITY, m1 = -INFINITY, l0 = 0.0f, l1 = 0.0f;
    const float scale = 0.125f;    // 64^-0.5

    const int r0s    = w * 16 + g;             // local q row of frag half 0
    const int row_g0 = qi * 64 + r0s;          // global q row
    const int row_g1 = row_g0 + 8;

    for (int j = jstart; j <= jend; j++) {
        __syncthreads();
        const float* kt = kb + (long)j * 64 * H_;
        const float* vt = vb + (long)j * 64 * H_;
        // FULL tile: 1024 float4 each = 128 thr x 8 iters  (R10 bug: was x4)
        #pragma unroll
        for (int i = 0; i < 8; i++) {
            int idx = tid + i * 128;
            int r = idx >> 4, cc = (idx & 15) * 4;
            float4 kv = *(const float4*)&kt[r * H_ + cc];
            float4 vv = *(const float4*)&vt[r * H_ + cc];
            *(uint4*)&ks[r * KS_S + cc] =
                make_uint4(f2t(kv.x), f2t(kv.y), f2t(kv.z), f2t(kv.w));
            *(uint4*)&vs[r * VS_S + cc] =
                make_uint4(f2t(vv.x), f2t(vv.y), f2t(vv.z), f2t(vv.w));
        }
        __syncthreads();

        // ---- S = Q K^T ----
        float sc[8][4];
        #pragma unroll
        for (int nt = 0; nt < 8; nt++)
            #pragma unroll
            for (int ci = 0; ci < 4; ci++) sc[nt][ci] = 0.0f;

        #pragma unroll
        for (int ks8 = 0; ks8 < 8; ks8++) {
            const int kk = ks8 * 8;
            uint32_t a0 = qs[(r0s    ) * QS_S + kk + t];
            uint32_t a1 = qs[(r0s + 8) * QS_S + kk + t];
            uint32_t a2 = qs[(r0s    ) * QS_S + kk + t + 4];
            uint32_t a3 = qs[(r0s + 8) * QS_S + kk + t + 4];
            #pragma unroll
            for (int nt = 0; nt < 8; nt++) {
                uint32_t b0 = ks[(nt * 8 + g) * KS_S + kk + t];
                uint32_t b1 = ks[(nt * 8 + g) * KS_S + kk + t + 4];
                mma_tf32(sc[nt], a0, a1, a2, a3, b0, b1);
            }
        }

        // scale + causal mask (diagonal tile only: j == qi)
        if (j == qi) {
            #pragma unroll
            for (int nt = 0; nt < 8; nt++) {
                int c0 = j * 64 + nt * 8 + 2 * t;
                sc[nt][0] = (c0     > row_g0) ? -INFINITY : sc[nt][0] * scale;
                sc[nt][1] = (c0 + 1 > row_g0) ? -INFINITY : sc[nt][1] * scale;
                sc[nt][2] = (c0     > row_g1) ? -INFINITY : sc[nt][2] * scale;
                sc[nt][3] = (c0 + 1 > row_g1) ? -INFINITY : sc[nt][3] * scale;
            }
        } else {
            #pragma unroll
            for (int nt = 0; nt < 8; nt++)
                #pragma unroll
                for (int ci = 0; ci < 4; ci++) sc[nt][ci] *= scale;
        }

        // ---- online softmax ----
        float mx0 = -INFINITY, mx1 = -INFINITY;
        #pragma unroll
        for (int nt = 0; nt < 8; nt++) {
            mx0 = fmaxf(mx0, fmaxf(sc[nt][0], sc[nt][1]));
            mx1 = fmaxf(mx1, fmaxf(sc[nt][2], sc[nt][3]));
        }
        #pragma unroll
        for (int off = 1; off < 4; off <<= 1) {
            mx0 = fmaxf(mx0, __shfl_xor_sync(0xffffffffu, mx0, off));
            mx1 = fmaxf(mx1, __shfl_xor_sync(0xffffffffu, mx1, off));
        }
        float mn0 = fmaxf(m0, mx0), mn1 = fmaxf(m1, mx1);
        float al0 = __expf(m0 - mn0), al1 = __expf(m1 - mn1);
        m0 = mn0; m1 = mn1;

        float rs0 = 0.0f, rs1 = 0.0f;
        #pragma unroll
        for (int nt = 0; nt < 8; nt++) {
            sc[nt][0] = __expf(sc[nt][0] - mn0);
            sc[nt][1] = __expf(sc[nt][1] - mn0);
            sc[nt][2] = __expf(sc[nt][2] - mn1);
            sc[nt][3] = __expf(sc[nt][3] - mn1);
            rs0 += sc[nt][0] + sc[nt][1];
            rs1 += sc[nt][2] + sc[nt][3];
        }
        #pragma unroll
        for (int off = 1; off < 4; off <<= 1) {
            rs0 += __shfl_xor_sync(0xffffffffu, rs0, off);
            rs1 += __shfl_xor_sync(0xffffffffu, rs1, off);
        }
        l0 = l0 * al0 + rs0;
        l1 = l1 * al1 + rs1;

        // rescale O, stage P (tf32) to smem (per-warp rows)
        #pragma unroll
        for (int nt = 0; nt < 8; nt++) {
            oc[nt][0] *= al0; oc[nt][1] *= al0;
            oc[nt][2] *= al1; oc[nt][3] *= al1;
            int cc = nt * 8 + 2 * t;
            *(uint2*)&ps[(r0s    ) * PS_S + cc] = make_uint2(f2t(sc[nt][0]), f2t(sc[nt][1]));
            *(uint2*)&ps[(r0s + 8) * PS_S + cc] = make_uint2(f2t(sc[nt][2]), f2t(sc[nt][3]));
        }
        __syncwarp();

        // ---- O += P V ----
        #pragma unroll
        for (int ks8 = 0; ks8 < 8; ks8++) {
            const int kk = ks8 * 8;
            uint32_t a0 = ps[(r0s    ) * PS_S + kk + t];
            uint32_t a1 = ps[(r0s + 8) * PS_S + kk + t];
            uint32_t a2 = ps[(r0s    ) * PS_S + kk + t + 4];
            uint32_t a3 = ps[(r0s + 8) * PS_S + kk + t + 4];
            #pragma unroll
            for (int nt = 0; nt < 8; nt++) {
                uint32_t b0 = vs[(kk + t    ) * VS_S + nt * 8 + g];
                uint32_t b1 = vs[(kk + t + 4) * VS_S + nt * 8 + g];
                mma_tf32(oc[nt], a0, a1, a2, a3, b0, b1);
            }
        }
    }

    // write partials (unnormalized O, m, l)
    float* P = g_part + ((size_t)((b * 32 + qi) * 4 + c)) * PART_STRIDE;
    #pragma unroll
    for (int nt = 0; nt < 8; nt++) {
        int cc = nt * 8 + 2 * t;
        *(float2*)&P[(r0s    ) * 64 + cc] = make_float2(oc[nt][0], oc[nt][1]);
        *(float2*)&P[(r0s + 8) * 64 + cc] = make_float2(oc[nt][2], oc[nt][3]);
    }
    if (t == 0) {
        P[4096 + r0s]     = m0;
        P[4096 + r0s + 8] = m1;
        P[4160 + r0s]     = l0;
        P[4160 + r0s + 8] = l1;
    }
}

// ---------------------------------------------------------------------------
// Kernel 3: combine split-K partials.  grid (32, 16), 256 threads.
// out[b][qi*64 + r][:] = sum_c e^{m_c - M} O_c[r][:] / L,  L = sum_c l_c e^{m_c-M}
// ---------------------------------------------------------------------------
__global__ __launch_bounds__(256) void combine_kernel(float* __restrict__ out)
{
    const int qi = blockIdx.x;
    const int b  = blockIdx.y;
    const int nch = (qi >> 3) + 1;
    const int tid = threadIdx.x;

    __shared__ float wgt[64][4];
    __shared__ float invl[64];

    const size_t base0 = (size_t)((b * 32 + qi) * 4) * PART_STRIDE;

    if (tid < 64) {
        float mv[4];
        float M = -INFINITY;
        for (int cc = 0; cc < nch; cc++) {
            mv[cc] = g_part[base0 + (size_t)cc * PART_STRIDE + 4096 + tid];
            M = fmaxf(M, mv[cc]);
        }
        float L = 0.0f;
        for (int cc = 0; cc < nch; cc++) {
            float wv = __expf(mv[cc] - M);
            wgt[tid][cc] = wv;
            L += wv * g_part[base0 + (size_t)cc * PART_STRIDE + 4160 + tid];
        }
        invl[tid] = 1.0f / L;
    }
    __syncthreads();

    float* ob = out + ((size_t)b * T_ + (size_t)qi * 64) * H_;
    #pragma unroll
    for (int i = 0; i < 16; i++) {
        int idx = tid + i * 256;       // 0..4095
        int r = idx >> 6, h = idx & 63;
        float a = 0.0f;
        for (int cc = 0; cc < nch; cc++)
            a += wgt[r][cc] * g_part[base0 + (size_t)cc * PART_STRIDE + r * 64 + h];
        ob[r * H_ + h] = a * invl[r];
    }
}

// ---------------------------------------------------------------------------
extern "C" void kernel_launch(void* const* d_in, const int* in_sizes, int n_in,
                              void* d_out, int out_size)
{
    const float* x  = (const float*)d_in[0];
    const float* Wk = (const float*)d_in[1];
    const float* Wq = (const float*)d_in[2];
    const float* Wv = (const float*)d_in[3];
    float* out = (float*)d_out;

    cudaFuncSetAttribute(proj_kernel, cudaFuncAttributeMaxDynamicSharedMemorySize,
                         PROJ_SMEM);
    cudaFuncSetAttribute(attn_kernel, cudaFuncAttributeMaxDynamicSharedMemorySize,
                         ATTN_SMEM);

    // Fused QKV projection: M = B*T = 32768 -> 512 tiles of 64 rows
    proj_kernel<<<(B_ * T_) / 64, 256, PROJ_SMEM>>>(x, Wk, Wq, Wv);

    // Flash attention partials: 80 (qi,chunk) work items x 16 batches
    attn_kernel<<<dim3(80, B_), 128, ATTN_SMEM>>>();

    // Combine partials -> output
    combine_kernel<<<dim3(32, B_), 256>>>(out);
}

// round 14
// speedup vs baseline: 1.6976x; 1.6976x over previous
#include <cuda_runtime.h>
#include <cuda_bf16.h>
#include <math.h>
#include <stdint.h>

// Problem constants
#define B_   16
#define T_   2048
#define E_   1024
#define H_   64

// Scratch (device globals: no allocation allowed)
__device__ float g_q[B_ * T_ * H_];
__device__ float g_k[B_ * T_ * H_];
__device__ float g_v[B_ * T_ * H_];
// Pre-transposed, hi/lo-split, bf16x2-packed weights:
// g_wt*[n * 512 + k2] packs W_s[2*k2][n&63] (lo16) and W_s[2*k2+1][n&63] (hi16),
// n = s*64 + col, s in {k,q,v}.
__device__ uint32_t g_wth[192 * 512];
__device__ uint32_t g_wtl[192 * 512];

// ---------------------------------------------------------------------------
// helpers
// ---------------------------------------------------------------------------
__device__ __forceinline__ uint32_t f2t(float x) {
    uint32_t r;
    asm("cvt.rna.tf32.f32 %0, %1;" : "=r"(r) : "f"(x));
    return r;
}

// tf32 warp MMA m16n8k8 (attention kernel)
__device__ __forceinline__ void mma_tf32(float c[4],
                                         uint32_t a0, uint32_t a1, uint32_t a2, uint32_t a3,
                                         uint32_t b0, uint32_t b1)
{
    asm volatile(
        "mma.sync.aligned.m16n8k8.row.col.f32.tf32.tf32.f32 "
        "{%0,%1,%2,%3}, {%4,%5,%6,%7}, {%8,%9}, {%0,%1,%2,%3};\n"
        : "+f"(c[0]), "+f"(c[1]), "+f"(c[2]), "+f"(c[3])
        : "r"(a0), "r"(a1), "r"(a2), "r"(a3), "r"(b0), "r"(b1));
}

// bf16 warp MMA m16n8k16 (projection kernel) — 2048 MACs/instr, 2x tf32 rate
__device__ __forceinline__ void mma_bf16(float c[4],
                                         uint32_t a0, uint32_t a1, uint32_t a2, uint32_t a3,
                                         uint32_t b0, uint32_t b1)
{
    asm volatile(
        "mma.sync.aligned.m16n8k16.row.col.f32.bf16.bf16.f32 "
        "{%0,%1,%2,%3}, {%4,%5,%6,%7}, {%8,%9}, {%0,%1,%2,%3};\n"
        : "+f"(c[0]), "+f"(c[1]), "+f"(c[2]), "+f"(c[3])
        : "r"(a0), "r"(a1), "r"(a2), "r"(a3), "r"(b0), "r"(b1));
}

// bf16 hi/lo split of two floats, packed bf16x2 (a -> low half = even k)
__device__ __forceinline__ void split_bf16x2(float a, float b,
                                             uint32_t& hi, uint32_t& lo) {
    __nv_bfloat16 ha = __float2bfloat16(a);
    __nv_bfloat16 hb = __float2bfloat16(b);
    __nv_bfloat16 la = __float2bfloat16(a - __bfloat162float(ha));
    __nv_bfloat16 lb = __float2bfloat16(b - __bfloat162float(hb));
    hi = (uint32_t)__bfloat16_as_ushort(ha) | ((uint32_t)__bfloat16_as_ushort(hb) << 16);
    lo = (uint32_t)__bfloat16_as_ushort(la) | ((uint32_t)__bfloat16_as_ushort(lb) << 16);
}

// ---------------------------------------------------------------------------
// Kernel 0: W transpose + bf16 hi/lo split + bf16x2 pack (once, tiny).
// 98304 output words per array; thread idx -> (n = idx>>9, k2 = idx&511).
// ---------------------------------------------------------------------------
__global__ __launch_bounds__(256) void wconv_kernel(
    const float* __restrict__ Wk,
    const float* __restrict__ Wq,
    const float* __restrict__ Wv)
{
    int idx = blockIdx.x * 256 + threadIdx.x;   // 0..98303
    int n  = idx >> 9;                          // 0..191
    int k2 = idx & 511;
    int s = n >> 6, nn = n & 63;
    const float* W = (s == 0) ? Wk : ((s == 1) ? Wq : Wv);
    float v0 = W[(2 * k2    ) * H_ + nn];
    float v1 = W[(2 * k2 + 1) * H_ + nn];
    uint32_t h, l;
    split_bf16x2(v0, v1, h, l);
    g_wth[idx] = h;
    g_wtl[idx] = l;
}

// ---------------------------------------------------------------------------
// Kernel 1: FUSED QKV projection via 3xBF16 MMA (m16n8k16).
// [k|q|v] = x @ [Wk|Wq|Wv].  Block: 128 threads (4 warps).
// M-tile 64, N = 192, K chunks of 32 (2 k16 steps).
// acc += xh*wh + xl*wh + xh*wl  (xl*wl dropped: ~2^-18 relative).
// smem word stride 20 (==20 mod 32): fragment reads hit 32 distinct banks.
// smem: xsh[64*20], xsl[64*20], wth[192*20], wtl[192*20] = 40960 B.
// ---------------------------------------------------------------------------
#define XS 20
#define WT 20
#define PROJ_SMEM ((64*XS*2 + 192*WT*2) * 4)   // 40960 B

__global__ __launch_bounds__(128) void proj_kernel(const float* __restrict__ x)
{
    extern __shared__ uint32_t psm[];
    uint32_t* xsh = psm;                   // 64*20
    uint32_t* xsl = xsh + 64 * XS;
    uint32_t* wth = xsl + 64 * XS;         // 192*20
    uint32_t* wtl = wth + 192 * WT;

    const int tid  = threadIdx.x;
    const int w    = tid >> 5;
    const int lane = tid & 31;
    const int g    = lane >> 2;
    const int t    = lane & 3;
    const long rowBase = (long)blockIdx.x * 64;

    const uint4* wsrc_h = (const uint4*)g_wth;   // row stride 128 uint4
    const uint4* wsrc_l = (const uint4*)g_wtl;

    float acc[24][4] = {};

    for (int ch = 0; ch < 32; ch++) {
        const int k0 = ch * 32;
        __syncthreads();   // previous MMA phase done with smem

        // X chunk: 64 rows x 32 k fp32 = 512 float4, 4 per thread.
        #pragma unroll
        for (int i = 0; i < 4; i++) {
            int idx = tid + i * 128;
            int r = idx >> 3, cq = (idx & 7) * 4;
            float4 v = *(const float4*)&x[(rowBase + r) * E_ + k0 + cq];
            uint32_t h0, l0, h1, l1;
            split_bf16x2(v.x, v.y, h0, l0);
            split_bf16x2(v.z, v.w, h1, l1);
            int off = r * XS + (cq >> 1);
            *(uint2*)&xsh[off] = make_uint2(h0, h1);
            *(uint2*)&xsl[off] = make_uint2(l0, l1);
        }
        // W chunk: 192 rows x 16 words (pre-packed) = 768 uint4 per array,
        // 6 per thread per array.
        #pragma unroll
        for (int i = 0; i < 6; i++) {
            int idx = tid + i * 128;       // 0..767
            int n = idx >> 2, q = idx & 3;
            *(uint4*)&wth[n * WT + q * 4] = wsrc_h[n * 128 + ch * 4 + q];
            *(uint4*)&wtl[n * WT + q * 4] = wsrc_l[n * 128 + ch * 4 + q];
        }
        __syncthreads();

        // MMA phase: 2 k16 steps x 24 nt x 3 terms
        #pragma unroll
        for (int ks = 0; ks < 2; ks++) {
            const int kk2 = ks * 8;
            const int r0 = w * 16 + g;
            uint32_t ah0 = xsh[(r0    ) * XS + kk2 + t];
            uint32_t ah1 = xsh[(r0 + 8) * XS + kk2 + t];
            uint32_t ah2 = xsh[(r0    ) * XS + kk2 + t + 4];
            uint32_t ah3 = xsh[(r0 + 8) * XS + kk2 + t + 4];
            uint32_t al0 = xsl[(r0    ) * XS + kk2 + t];
            uint32_t al1 = xsl[(r0 + 8) * XS + kk2 + t];
            uint32_t al2 = xsl[(r0    ) * XS + kk2 + t + 4];
            uint32_t al3 = xsl[(r0 + 8) * XS + kk2 + t + 4];
            #pragma unroll
            for (int nt = 0; nt < 24; nt++) {
                uint32_t bh0 = wth[(nt * 8 + g) * WT + kk2 + t];
                uint32_t bh1 = wth[(nt * 8 + g) * WT + kk2 + t + 4];
                uint32_t bl0 = wtl[(nt * 8 + g) * WT + kk2 + t];
                uint32_t bl1 = wtl[(nt * 8 + g) * WT + kk2 + t + 4];
                mma_bf16(acc[nt], ah0, ah1, ah2, ah3, bh0, bh1);
                mma_bf16(acc[nt], al0, al1, al2, al3, bh0, bh1);
                mma_bf16(acc[nt], ah0, ah1, ah2, ah3, bl0, bl1);
            }
        }
    }

    // store: nt 0..7 -> g_k, 8..15 -> g_q, 16..23 -> g_v
    const long r0 = rowBase + w * 16 + g;
    #pragma unroll
    for (int nt = 0; nt < 24; nt++) {
        float* o = (nt < 8) ? g_k : ((nt < 16) ? g_q : g_v);
        int c = (nt & 7) * 8 + 2 * t;
        *(float2*)&o[(r0    ) * H_ + c] = make_float2(acc[nt][0], acc[nt][1]);
        *(float2*)&o[(r0 + 8) * H_ + c] = make_float2(acc[nt][2], acc[nt][3]);
    }
}

// ---------------------------------------------------------------------------
// Kernel 2: causal flash attention, tf32 MMA (R8 version, measured 134us).
// Block: 128 threads (4 warps). Q-tile 64 x K-tile 64. Warp w owns q-rows
// [w*16, w*16+16). S = Q K^T and O += P V both via m16n8k8.
// smem (uint32 tf32): qs[64][68], ks[64][68], vs[64][72], ps[64][68]
// ---------------------------------------------------------------------------
#define QS_S 68
#define KS_S 68
#define VS_S 72
#define PS_S 68
#define ATTN_SMEM ((64*QS_S + 64*KS_S + 64*VS_S + 64*PS_S) * 4)  // 70656 B

__global__ __launch_bounds__(128) void attn_kernel(float* __restrict__ out)
{
    extern __shared__ uint32_t asm_[];
    uint32_t* qs = asm_;
    uint32_t* ks = qs + 64 * QS_S;
    uint32_t* vs = ks + 64 * KS_S;
    uint32_t* ps = vs + 64 * VS_S;

    const int qi = blockIdx.x;     // query tile 0..31
    const int b  = blockIdx.y;     // batch
    const int tid  = threadIdx.x;
    const int w    = tid >> 5;
    const int lane = tid & 31;
    const int g    = lane >> 2;
    const int t    = lane & 3;

    const float* qb = g_q + ((long)b * T_ + (long)qi * 64) * H_;
    const float* kb = g_k + (long)b * T_ * H_;
    const float* vb = g_v + (long)b * T_ * H_;

    // load Q tile -> tf32 smem
    #pragma unroll
    for (int i = 0; i < 8; i++) {
        int idx = tid + i * 128;
        int r = idx >> 4, c = (idx & 15) * 4;
        float4 v = *(const float4*)&qb[r * H_ + c];
        *(uint4*)&qs[r * QS_S + c] =
            make_uint4(f2t(v.x), f2t(v.y), f2t(v.z), f2t(v.w));
    }

    float oc[8][4] = {};
    float m0 = -INFINITY, m1 = -INFINITY, l0 = 0.0f, l1 = 0.0f;
    const float scale = 0.125f;    // 64^-0.5

    const int row_g0 = qi * 64 + w * 16 + g;   // global q row of frag half 0
    const int row_g1 = row_g0 + 8;
    const int r0s = w * 16 + g;

    for (int j = 0; j <= qi; j++) {
        __syncthreads();
        const float* kt = kb + (long)j * 64 * H_;
        const float* vt = vb + (long)j * 64 * H_;
        #pragma unroll
        for (int i = 0; i < 8; i++) {
            int idx = tid + i * 128;
            int r = idx >> 4, c = (idx & 15) * 4;
            float4 kv = *(const float4*)&kt[r * H_ + c];
            float4 vv = *(const float4*)&vt[r * H_ + c];
            *(uint4*)&ks[r * KS_S + c] =
                make_uint4(f2t(kv.x), f2t(kv.y), f2t(kv.z), f2t(kv.w));
            *(uint4*)&vs[r * VS_S + c] =
                make_uint4(f2t(vv.x), f2t(vv.y), f2t(vv.z), f2t(vv.w));
        }
        __syncthreads();

        // ---- S = Q K^T ----
        float sc[8][4];
        #pragma unroll
        for (int nt = 0; nt < 8; nt++)
            #pragma unroll
            for (int ci = 0; ci < 4; ci++) sc[nt][ci] = 0.0f;

        #pragma unroll
        for (int ks8 = 0; ks8 < 8; ks8++) {
            const int kk = ks8 * 8;
            uint32_t a0 = qs[(r0s    ) * QS_S + kk + t];
            uint32_t a1 = qs[(r0s + 8) * QS_S + kk + t];
            uint32_t a2 = qs[(r0s    ) * QS_S + kk + t + 4];
            uint32_t a3 = qs[(r0s + 8) * QS_S + kk + t + 4];
            #pragma unroll
            for (int nt = 0; nt < 8; nt++) {
                uint32_t b0 = ks[(nt * 8 + g) * KS_S + kk + t];
                uint32_t b1 = ks[(nt * 8 + g) * KS_S + kk + t + 4];
                mma_tf32(sc[nt], a0, a1, a2, a3, b0, b1);
            }
        }

        // scale + causal mask (diagonal tile only)
        if (j == qi) {
            #pragma unroll
            for (int nt = 0; nt < 8; nt++) {
                int c0 = j * 64 + nt * 8 + 2 * t;
                sc[nt][0] = (c0     > row_g0) ? -INFINITY : sc[nt][0] * scale;
                sc[nt][1] = (c0 + 1 > row_g0) ? -INFINITY : sc[nt][1] * scale;
                sc[nt][2] = (c0     > row_g1) ? -INFINITY : sc[nt][2] * scale;
                sc[nt][3] = (c0 + 1 > row_g1) ? -INFINITY : sc[nt][3] * scale;
            }
        } else {
            #pragma unroll
            for (int nt = 0; nt < 8; nt++)
                #pragma unroll
                for (int ci = 0; ci < 4; ci++) sc[nt][ci] *= scale;
        }

        // ---- online softmax ----
        float mx0 = -INFINITY, mx1 = -INFINITY;
        #pragma unroll
        for (int nt = 0; nt < 8; nt++) {
            mx0 = fmaxf(mx0, fmaxf(sc[nt][0], sc[nt][1]));
            mx1 = fmaxf(mx1, fmaxf(sc[nt][2], sc[nt][3]));
        }
        #pragma unroll
        for (int off = 1; off < 4; off <<= 1) {
            mx0 = fmaxf(mx0, __shfl_xor_sync(0xffffffffu, mx0, off));
            mx1 = fmaxf(mx1, __shfl_xor_sync(0xffffffffu, mx1, off));
        }
        float mn0 = fmaxf(m0, mx0), mn1 = fmaxf(m1, mx1);
        float al0 = __expf(m0 - mn0), al1 = __expf(m1 - mn1);
        m0 = mn0; m1 = mn1;

        float rs0 = 0.0f, rs1 = 0.0f;
        #pragma unroll
        for (int nt = 0; nt < 8; nt++) {
            sc[nt][0] = __expf(sc[nt][0] - mn0);
            sc[nt][1] = __expf(sc[nt][1] - mn0);
            sc[nt][2] = __expf(sc[nt][2] - mn1);
            sc[nt][3] = __expf(sc[nt][3] - mn1);
            rs0 += sc[nt][0] + sc[nt][1];
            rs1 += sc[nt][2] + sc[nt][3];
        }
        #pragma unroll
        for (int off = 1; off < 4; off <<= 1) {
            rs0 += __shfl_xor_sync(0xffffffffu, rs0, off);
            rs1 += __shfl_xor_sync(0xffffffffu, rs1, off);
        }
        l0 = l0 * al0 + rs0;
        l1 = l1 * al1 + rs1;

        // rescale O, stage P (tf32) to smem (per-warp rows)
        #pragma unroll
        for (int nt = 0; nt < 8; nt++) {
            oc[nt][0] *= al0; oc[nt][1] *= al0;
            oc[nt][2] *= al1; oc[nt][3] *= al1;
            int c = nt * 8 + 2 * t;
            *(uint2*)&ps[(r0s    ) * PS_S + c] = make_uint2(f2t(sc[nt][0]), f2t(sc[nt][1]));
            *(uint2*)&ps[(r0s + 8) * PS_S + c] = make_uint2(f2t(sc[nt][2]), f2t(sc[nt][3]));
        }
        __syncwarp();

        // ---- O += P V ----
        #pragma unroll
        for (int ks8 = 0; ks8 < 8; ks8++) {
            const int kk = ks8 * 8;
            uint32_t a0 = ps[(r0s    ) * PS_S + kk + t];
            uint32_t a1 = ps[(r0s + 8) * PS_S + kk + t];
            uint32_t a2 = ps[(r0s    ) * PS_S + kk + t + 4];
            uint32_t a3 = ps[(r0s + 8) * PS_S + kk + t + 4];
            #pragma unroll
            for (int nt = 0; nt < 8; nt++) {
                uint32_t b0 = vs[(kk + t    ) * VS_S + nt * 8 + g];
                uint32_t b1 = vs[(kk + t + 4) * VS_S + nt * 8 + g];
                mma_tf32(oc[nt], a0, a1, a2, a3, b0, b1);
            }
        }
    }

    // normalize + write out
    float inv0 = 1.0f / l0, inv1 = 1.0f / l1;
    float* ob = out + ((long)b * T_) * H_;
    #pragma unroll
    for (int nt = 0; nt < 8; nt++) {
        int c = nt * 8 + 2 * t;
        *(float2*)&ob[(long)row_g0 * H_ + c] =
            make_float2(oc[nt][0] * inv0, oc[nt][1] * inv0);
        *(float2*)&ob[(long)row_g1 * H_ + c] =
            make_float2(oc[nt][2] * inv1, oc[nt][3] * inv1);
    }
}

// ---------------------------------------------------------------------------
extern "C" void kernel_launch(void* const* d_in, const int* in_sizes, int n_in,
                              void* d_out, int out_size)
{
    const float* x  = (const float*)d_in[0];
    const float* Wk = (const float*)d_in[1];
    const float* Wq = (const float*)d_in[2];
    const float* Wv = (const float*)d_in[3];
    float* out = (float*)d_out;

    cudaFuncSetAttribute(proj_kernel, cudaFuncAttributeMaxDynamicSharedMemorySize,
                         PROJ_SMEM);
    cudaFuncSetAttribute(attn_kernel, cudaFuncAttributeMaxDynamicSharedMemorySize,
                         ATTN_SMEM);

    // W transpose + bf16 split + pack (192 x 512 words)
    wconv_kernel<<<384, 256>>>(Wk, Wq, Wv);

    // Fused QKV projection: 512 M-tiles of 64 rows
    proj_kernel<<<512, 128, PROJ_SMEM>>>(x);

    // Flash attention: (32 q-tiles, 16 batches)
    attn_kernel<<<dim3(T_ / 64, B_), 128, ATTN_SMEM>>>(out);
}

// round 15
// speedup vs baseline: 2.3438x; 1.3806x over previous
#include <cuda_runtime.h>
#include <cuda_bf16.h>
#include <cuda_fp16.h>
#include <math.h>
#include <stdint.h>

// Problem constants
#define B_   16
#define T_   2048
#define E_   1024
#define H_   64

// Scratch (device globals: no allocation allowed)
// q,k,v stored as fp16x2 packed along head-dim d: [b*T + s][d/2] (32 words/row)
__device__ uint32_t g_q16[B_ * T_ * 32];
__device__ uint32_t g_k16[B_ * T_ * 32];
__device__ uint32_t g_v16[B_ * T_ * 32];
// v transposed per batch: [b][d][s/2] packed along s (1024 words per d-row)
__device__ uint32_t g_vt16[(size_t)B_ * 64 * 1024];
// Pre-transposed, hi/lo-split, bf16x2-packed weights (proj):
__device__ uint32_t g_wth[192 * 512];
__device__ uint32_t g_wtl[192 * 512];

// ---------------------------------------------------------------------------
// helpers
// ---------------------------------------------------------------------------
// bf16 warp MMA m16n8k16 (projection)
__device__ __forceinline__ void mma_bf16(float c[4],
                                         uint32_t a0, uint32_t a1, uint32_t a2, uint32_t a3,
                                         uint32_t b0, uint32_t b1)
{
    asm volatile(
        "mma.sync.aligned.m16n8k16.row.col.f32.bf16.bf16.f32 "
        "{%0,%1,%2,%3}, {%4,%5,%6,%7}, {%8,%9}, {%0,%1,%2,%3};\n"
        : "+f"(c[0]), "+f"(c[1]), "+f"(c[2]), "+f"(c[3])
        : "r"(a0), "r"(a1), "r"(a2), "r"(a3), "r"(b0), "r"(b1));
}

// fp16 warp MMA m16n8k16 (attention) — same 10-bit mantissa as tf32, 2x MACs
__device__ __forceinline__ void mma_fp16(float c[4],
                                         uint32_t a0, uint32_t a1, uint32_t a2, uint32_t a3,
                                         uint32_t b0, uint32_t b1)
{
    asm volatile(
        "mma.sync.aligned.m16n8k16.row.col.f32.f16.f16.f32 "
        "{%0,%1,%2,%3}, {%4,%5,%6,%7}, {%8,%9}, {%0,%1,%2,%3};\n"
        : "+f"(c[0]), "+f"(c[1]), "+f"(c[2]), "+f"(c[3])
        : "r"(a0), "r"(a1), "r"(a2), "r"(a3), "r"(b0), "r"(b1));
}

__device__ __forceinline__ uint32_t pack_h2(float a, float b) {
    __half2 h = __floats2half2_rn(a, b);   // a -> low half
    return *(uint32_t*)&h;
}

// bf16 hi/lo split of two floats, packed bf16x2 (a -> low half = even k)
__device__ __forceinline__ void split_bf16x2(float a, float b,
                                             uint32_t& hi, uint32_t& lo) {
    __nv_bfloat16 ha = __float2bfloat16(a);
    __nv_bfloat16 hb = __float2bfloat16(b);
    __nv_bfloat16 la = __float2bfloat16(a - __bfloat162float(ha));
    __nv_bfloat16 lb = __float2bfloat16(b - __bfloat162float(hb));
    hi = (uint32_t)__bfloat16_as_ushort(ha) | ((uint32_t)__bfloat16_as_ushort(hb) << 16);
    lo = (uint32_t)__bfloat16_as_ushort(la) | ((uint32_t)__bfloat16_as_ushort(lb) << 16);
}

#define CP_ASYNC16(smem_u32, gptr) \
    asm volatile("cp.async.cg.shared.global [%0], [%1], 16;" \
                 :: "r"(smem_u32), "l"(gptr) : "memory")
#define CP_ASYNC_COMMIT() asm volatile("cp.async.commit_group;" ::: "memory")
#define CP_ASYNC_WAIT0()  asm volatile("cp.async.wait_group 0;" ::: "memory")

__device__ __forceinline__ uint32_t smem_u32(const void* p) {
    uint32_t a;
    asm("{ .reg .u64 t; cvta.to.shared.u64 t, %1; cvt.u32.u64 %0, t; }"
        : "=r"(a) : "l"(p));
    return a;
}

// ---------------------------------------------------------------------------
// Kernel 0: W transpose + bf16 hi/lo split + bf16x2 pack (once, tiny).
// ---------------------------------------------------------------------------
__global__ __launch_bounds__(256) void wconv_kernel(
    const float* __restrict__ Wk,
    const float* __restrict__ Wq,
    const float* __restrict__ Wv)
{
    int idx = blockIdx.x * 256 + threadIdx.x;   // 0..98303
    int n  = idx >> 9;                          // 0..191
    int k2 = idx & 511;
    int s = n >> 6, nn = n & 63;
    const float* W = (s == 0) ? Wk : ((s == 1) ? Wq : Wv);
    float v0 = W[(2 * k2    ) * H_ + nn];
    float v1 = W[(2 * k2 + 1) * H_ + nn];
    uint32_t h, l;
    split_bf16x2(v0, v1, h, l);
    g_wth[idx] = h;
    g_wtl[idx] = l;
}

// ---------------------------------------------------------------------------
// Kernel 1: FUSED QKV projection via 3xBF16 MMA (m16n8k16).  (R14 core,
// measured; + cp.async for W, + fp16x2-packed epilogue.)
// Block: 128 threads (4 warps). M-tile 64, N = 192, K chunks of 32.
// ---------------------------------------------------------------------------
#define XS 20
#define WT 20
#define PROJ_SMEM ((64*XS*2 + 192*WT*2) * 4)   // 40960 B

__global__ __launch_bounds__(128) void proj_kernel(const float* __restrict__ x)
{
    extern __shared__ uint32_t psm[];
    uint32_t* xsh = psm;                   // 64*20
    uint32_t* xsl = xsh + 64 * XS;
    uint32_t* wth = xsl + 64 * XS;         // 192*20
    uint32_t* wtl = wth + 192 * WT;

    const int tid  = threadIdx.x;
    const int w    = tid >> 5;
    const int lane = tid & 31;
    const int g    = lane >> 2;
    const int t    = lane & 3;
    const long rowBase = (long)blockIdx.x * 64;

    const uint4* wsrc_h = (const uint4*)g_wth;   // row stride 128 uint4
    const uint4* wsrc_l = (const uint4*)g_wtl;
    const uint32_t wth_s = smem_u32(wth);
    const uint32_t wtl_s = smem_u32(wtl);

    float acc[24][4] = {};

    for (int ch = 0; ch < 32; ch++) {
        const int k0 = ch * 32;
        __syncthreads();   // previous MMA phase done with smem

        // W chunk via cp.async (pre-packed, no reg round-trip); overlaps X convert
        #pragma unroll
        for (int i = 0; i < 6; i++) {
            int idx = tid + i * 128;       // 0..767
            int n = idx >> 2, q = idx & 3;
            uint32_t doff = (uint32_t)(n * WT + q * 4) * 4;
            CP_ASYNC16(wth_s + doff, &wsrc_h[n * 128 + ch * 4 + q]);
            CP_ASYNC16(wtl_s + doff, &wsrc_l[n * 128 + ch * 4 + q]);
        }
        CP_ASYNC_COMMIT();

        // X chunk: 64 rows x 32 k fp32 = 512 float4, 4 per thread.
        #pragma unroll
        for (int i = 0; i < 4; i++) {
            int idx = tid + i * 128;
            int r = idx >> 3, cq = (idx & 7) * 4;
            float4 v = *(const float4*)&x[(rowBase + r) * E_ + k0 + cq];
            uint32_t h0, l0, h1, l1;
            split_bf16x2(v.x, v.y, h0, l0);
            split_bf16x2(v.z, v.w, h1, l1);
            int off = r * XS + (cq >> 1);
            *(uint2*)&xsh[off] = make_uint2(h0, h1);
            *(uint2*)&xsl[off] = make_uint2(l0, l1);
        }
        CP_ASYNC_WAIT0();
        __syncthreads();

        // MMA phase: 2 k16 steps x 24 nt x 3 terms
        #pragma unroll
        for (int ks = 0; ks < 2; ks++) {
            const int kk2 = ks * 8;
            const int r0 = w * 16 + g;
            uint32_t ah0 = xsh[(r0    ) * XS + kk2 + t];
            uint32_t ah1 = xsh[(r0 + 8) * XS + kk2 + t];
            uint32_t ah2 = xsh[(r0    ) * XS + kk2 + t + 4];
            uint32_t ah3 = xsh[(r0 + 8) * XS + kk2 + t + 4];
            uint32_t al0 = xsl[(r0    ) * XS + kk2 + t];
            uint32_t al1 = xsl[(r0 + 8) * XS + kk2 + t];
            uint32_t al2 = xsl[(r0    ) * XS + kk2 + t + 4];
            uint32_t al3 = xsl[(r0 + 8) * XS + kk2 + t + 4];
            #pragma unroll
            for (int nt = 0; nt < 24; nt++) {
                uint32_t bh0 = wth[(nt * 8 + g) * WT + kk2 + t];
                uint32_t bh1 = wth[(nt * 8 + g) * WT + kk2 + t + 4];
                uint32_t bl0 = wtl[(nt * 8 + g) * WT + kk2 + t];
                uint32_t bl1 = wtl[(nt * 8 + g) * WT + kk2 + t + 4];
                mma_bf16(acc[nt], ah0, ah1, ah2, ah3, bh0, bh1);
                mma_bf16(acc[nt], al0, al1, al2, al3, bh0, bh1);
                mma_bf16(acc[nt], ah0, ah1, ah2, ah3, bl0, bl1);
            }
        }
    }

    // store fp16x2 packed along d: word (row)*32 + (nt&7)*4 + t
    const long r0 = rowBase + w * 16 + g;
    #pragma unroll
    for (int nt = 0; nt < 24; nt++) {
        uint32_t* o = (nt < 8) ? g_k16 : ((nt < 16) ? g_q16 : g_v16);
        int wd = (nt & 7) * 4 + t;
        o[(r0    ) * 32 + wd] = pack_h2(acc[nt][0], acc[nt][1]);
        o[(r0 + 8) * 32 + wd] = pack_h2(acc[nt][2], acc[nt][3]);
    }
}

// ---------------------------------------------------------------------------
// Kernel 1b: V transpose. g_v16 [b*T+s][d/2] -> g_vt16 [b][d][s/2].
// One block per (b, 64-row s-tile). smem-tiled, fully coalesced both sides.
// ---------------------------------------------------------------------------
__global__ __launch_bounds__(256) void vtrans_kernel()
{
    __shared__ __half sm[64][80];   // [d][s], row stride 160 B (16B aligned)
    const int st = blockIdx.x;      // s-tile 0..31
    const int b  = blockIdx.y;
    const int tid = threadIdx.x;

    // in: 64 s-rows x 32 words; 2048 words / 256 thr = 8 each
    #pragma unroll
    for (int i = 0; i < 8; i++) {
        int idx = tid + i * 256;
        int s = idx >> 5, wd = idx & 31;
        uint32_t v = g_v16[((long)b * T_ + st * 64 + s) * 32 + wd];
        __half2 h = *(__half2*)&v;
        sm[2 * wd    ][s] = __low2half(h);
        sm[2 * wd + 1][s] = __high2half(h);
    }
    __syncthreads();

    // out: 64 d-rows x 32 words (s-pairs); coalesced along s
    #pragma unroll
    for (int i = 0; i < 8; i++) {
        int idx = tid + i * 256;
        int d = idx >> 5, q = idx & 31;
        uint32_t v = *(uint32_t*)&sm[d][2 * q];
        g_vt16[((size_t)b * 64 + d) * 1024 + st * 32 + q] = v;
    }
}

// ---------------------------------------------------------------------------
// Kernel 2: causal flash attention, fp16 m16n8k16 MMA throughout.
// Block: 128 threads (4 warps). Q-tile 64 x K-tile 64. Warp w owns q-rows
// [w*16, w*16+16). All operands pre-packed fp16x2 (no cvt in the loop).
// smem word arrays, stride 36 (==4 mod 32 -> frag reads conflict-free;
// 36*4=144=9*16 -> uint4 ops stay 16B-aligned).
// qs[64][36] (d-packed), ks[64][36] (d-packed), vts[64][36] (s-packed,
// from g_vt16), ps[64][36] (s-packed P). Total 36864 B -> 4+ CTAs/SM.
// ---------------------------------------------------------------------------
#define AS 36
#define ATTN_SMEM (4 * 64 * AS * 4)   // 36864 B

__global__ __launch_bounds__(128) void attn_kernel(float* __restrict__ out)
{
    extern __shared__ uint32_t asm_[];
    uint32_t* qs  = asm_;
    uint32_t* ks  = qs  + 64 * AS;
    uint32_t* vts = ks  + 64 * AS;
    uint32_t* ps  = vts + 64 * AS;

    const int qi = blockIdx.x;     // query tile 0..31
    const int b  = blockIdx.y;     // batch
    const int tid  = threadIdx.x;
    const int w    = tid >> 5;
    const int lane = tid & 31;
    const int g    = lane >> 2;
    const int t    = lane & 3;

    const uint32_t* qb  = g_q16 + ((long)b * T_ + (long)qi * 64) * 32;
    const uint32_t* kb  = g_k16 + (long)b * T_ * 32;
    const uint32_t* vtb = g_vt16 + (size_t)b * 64 * 1024;

    // load Q tile (64 rows x 32 words): 512 uint4 / 128 thr = 4 each
    #pragma unroll
    for (int i = 0; i < 4; i++) {
        int idx = tid + i * 128;
        int r = idx >> 3, q4 = (idx & 7) * 4;
        *(uint4*)&qs[r * AS + q4] = *(const uint4*)&qb[r * 32 + q4];
    }

    float oc[8][4] = {};
    float m0 = -INFINITY, m1 = -INFINITY, l0 = 0.0f, l1 = 0.0f;
    const float scale = 0.125f;    // 64^-0.5

    const int r0s    = w * 16 + g;
    const int row_g0 = qi * 64 + r0s;
    const int row_g1 = row_g0 + 8;

    for (int j = 0; j <= qi; j++) {
        __syncthreads();
        // K tile rows j*64.. (d-packed); V tile from vt: 64 d-rows, words j*32..
        #pragma unroll
        for (int i = 0; i < 4; i++) {
            int idx = tid + i * 128;
            int r = idx >> 3, q4 = (idx & 7) * 4;
            *(uint4*)&ks [r * AS + q4] = *(const uint4*)&kb [((long)j * 64 + r) * 32 + q4];
            *(uint4*)&vts[r * AS + q4] = *(const uint4*)&vtb[(size_t)r * 1024 + j * 32 + q4];
        }
        __syncthreads();

        // ---- S = Q K^T  (4 k16 steps over d) ----
        float sc[8][4];
        #pragma unroll
        for (int nt = 0; nt < 8; nt++)
            #pragma unroll
            for (int ci = 0; ci < 4; ci++) sc[nt][ci] = 0.0f;

        #pragma unroll
        for (int ks4 = 0; ks4 < 4; ks4++) {
            const int kk2 = ks4 * 8;
            uint32_t a0 = qs[(r0s    ) * AS + kk2 + t];
            uint32_t a1 = qs[(r0s + 8) * AS + kk2 + t];
            uint32_t a2 = qs[(r0s    ) * AS + kk2 + t + 4];
            uint32_t a3 = qs[(r0s + 8) * AS + kk2 + t + 4];
            #pragma unroll
            for (int nt = 0; nt < 8; nt++) {
                uint32_t b0 = ks[(nt * 8 + g) * AS + kk2 + t];
                uint32_t b1 = ks[(nt * 8 + g) * AS + kk2 + t + 4];
                mma_fp16(sc[nt], a0, a1, a2, a3, b0, b1);
            }
        }

        // scale + causal mask (diagonal tile only)
        if (j == qi) {
            #pragma unroll
            for (int nt = 0; nt < 8; nt++) {
                int c0 = j * 64 + nt * 8 + 2 * t;
                sc[nt][0] = (c0     > row_g0) ? -INFINITY : sc[nt][0] * scale;
                sc[nt][1] = (c0 + 1 > row_g0) ? -INFINITY : sc[nt][1] * scale;
                sc[nt][2] = (c0     > row_g1) ? -INFINITY : sc[nt][2] * scale;
                sc[nt][3] = (c0 + 1 > row_g1) ? -INFINITY : sc[nt][3] * scale;
            }
        } else {
            #pragma unroll
            for (int nt = 0; nt < 8; nt++)
                #pragma unroll
                for (int ci = 0; ci < 4; ci++) sc[nt][ci] *= scale;
        }

        // ---- online softmax ----
        float mx0 = -INFINITY, mx1 = -INFINITY;
        #pragma unroll
        for (int nt = 0; nt < 8; nt++) {
            mx0 = fmaxf(mx0, fmaxf(sc[nt][0], sc[nt][1]));
            mx1 = fmaxf(mx1, fmaxf(sc[nt][2], sc[nt][3]));
        }
        #pragma unroll
        for (int off = 1; off < 4; off <<= 1) {
            mx0 = fmaxf(mx0, __shfl_xor_sync(0xffffffffu, mx0, off));
            mx1 = fmaxf(mx1, __shfl_xor_sync(0xffffffffu, mx1, off));
        }
        float mn0 = fmaxf(m0, mx0), mn1 = fmaxf(m1, mx1);
        float al0 = __expf(m0 - mn0), al1 = __expf(m1 - mn1);
        m0 = mn0; m1 = mn1;

        float rs0 = 0.0f, rs1 = 0.0f;
        #pragma unroll
        for (int nt = 0; nt < 8; nt++) {
            sc[nt][0] = __expf(sc[nt][0] - mn0);
            sc[nt][1] = __expf(sc[nt][1] - mn0);
            sc[nt][2] = __expf(sc[nt][2] - mn1);
            sc[nt][3] = __expf(sc[nt][3] - mn1);
            rs0 += sc[nt][0] + sc[nt][1];
            rs1 += sc[nt][2] + sc[nt][3];
        }
        #pragma unroll
        for (int off = 1; off < 4; off <<= 1) {
            rs0 += __shfl_xor_sync(0xffffffffu, rs0, off);
            rs1 += __shfl_xor_sync(0xffffffffu, rs1, off);
        }
        l0 = l0 * al0 + rs0;
        l1 = l1 * al1 + rs1;

        // rescale O, stage P (fp16x2 packed along s) to smem (per-warp rows)
        #pragma unroll
        for (int nt = 0; nt < 8; nt++) {
            oc[nt][0] *= al0; oc[nt][1] *= al0;
            oc[nt][2] *= al1; oc[nt][3] *= al1;
            int wd = nt * 4 + t;           // word index = (nt*8 + 2t)/2
            ps[(r0s    ) * AS + wd] = pack_h2(sc[nt][0], sc[nt][1]);
            ps[(r0s + 8) * AS + wd] = pack_h2(sc[nt][2], sc[nt][3]);
        }
        __syncwarp();

        // ---- O += P V  (4 k16 steps over s; B from transposed V) ----
        #pragma unroll
        for (int ks4 = 0; ks4 < 4; ks4++) {
            const int kk2 = ks4 * 8;
            uint32_t a0 = ps[(r0s    ) * AS + kk2 + t];
            uint32_t a1 = ps[(r0s + 8) * AS + kk2 + t];
            uint32_t a2 = ps[(r0s    ) * AS + kk2 + t + 4];
            uint32_t a3 = ps[(r0s + 8) * AS + kk2 + t + 4];
            #pragma unroll
            for (int nt = 0; nt < 8; nt++) {
                uint32_t b0 = vts[(nt * 8 + g) * AS + kk2 + t];
                uint32_t b1 = vts[(nt * 8 + g) * AS + kk2 + t + 4];
                mma_fp16(oc[nt], a0, a1, a2, a3, b0, b1);
            }
        }
    }

    // normalize + write out (fp32)
    float inv0 = 1.0f / l0, inv1 = 1.0f / l1;
    float* ob = out + ((long)b * T_) * H_;
    #pragma unroll
    for (int nt = 0; nt < 8; nt++) {
        int c = nt * 8 + 2 * t;
        *(float2*)&ob[(long)row_g0 * H_ + c] =
            make_float2(oc[nt][0] * inv0, oc[nt][1] * inv0);
        *(float2*)&ob[(long)row_g1 * H_ + c] =
            make_float2(oc[nt][2] * inv1, oc[nt][3] * inv1);
    }
}

// ---------------------------------------------------------------------------
extern "C" void kernel_launch(void* const* d_in, const int* in_sizes, int n_in,
                              void* d_out, int out_size)
{
    const float* x  = (const float*)d_in[0];
    const float* Wk = (const float*)d_in[1];
    const float* Wq = (const float*)d_in[2];
    const float* Wv = (const float*)d_in[3];
    float* out = (float*)d_out;

    cudaFuncSetAttribute(proj_kernel, cudaFuncAttributeMaxDynamicSharedMemorySize,
                         PROJ_SMEM);
    cudaFuncSetAttribute(attn_kernel, cudaFuncAttributeMaxDynamicSharedMemorySize,
                         ATTN_SMEM);

    // W transpose + bf16 split + pack
    wconv_kernel<<<384, 256>>>(Wk, Wq, Wv);

    // Fused QKV projection: 512 M-tiles of 64 rows
    proj_kernel<<<512, 128, PROJ_SMEM>>>(x);

    // V transpose: (32 s-tiles, 16 batches)
    vtrans_kernel<<<dim3(32, B_), 256>>>();

    // Flash attention: (32 q-tiles, 16 batches)
    attn_kernel<<<dim3(T_ / 64, B_), 128, ATTN_SMEM>>>(out);
}

// round 16
// speedup vs baseline: 3.6065x; 1.5388x over previous
#include <cuda_runtime.h>
#include <cuda_bf16.h>
#include <cuda_fp16.h>
#include <math.h>
#include <stdint.h>

// Problem constants
#define B_   16
#define T_   2048
#define E_   1024
#define H_   64

// Scratch (device globals: no allocation allowed)
// q,k,v stored as fp16x2 packed along head-dim d: [b*T + s][d/2] (32 words/row)
__device__ uint32_t g_q16[B_ * T_ * 32];
__device__ uint32_t g_k16[B_ * T_ * 32];
__device__ uint32_t g_v16[B_ * T_ * 32];
// v transposed per batch: [b][d][s/2] packed along s (1024 words per d-row)
__device__ uint32_t g_vt16[(size_t)B_ * 64 * 1024];
// Pre-transposed fp16x2-packed weights: g_wt16[n*512 + k2] = (W[2k2][n&63], W[2k2+1][n&63]),
// n = s*64 + col, s in {k,q,v}
__device__ uint32_t g_wt16[192 * 512];

// ---------------------------------------------------------------------------
// helpers
// ---------------------------------------------------------------------------
// fp16 warp MMA m16n8k16 — same 10-bit mantissa as tf32, 2x MACs/instr
__device__ __forceinline__ void mma_fp16(float c[4],
                                         uint32_t a0, uint32_t a1, uint32_t a2, uint32_t a3,
                                         uint32_t b0, uint32_t b1)
{
    asm volatile(
        "mma.sync.aligned.m16n8k16.row.col.f32.f16.f16.f32 "
        "{%0,%1,%2,%3}, {%4,%5,%6,%7}, {%8,%9}, {%0,%1,%2,%3};\n"
        : "+f"(c[0]), "+f"(c[1]), "+f"(c[2]), "+f"(c[3])
        : "r"(a0), "r"(a1), "r"(a2), "r"(a3), "r"(b0), "r"(b1));
}

__device__ __forceinline__ uint32_t pack_h2(float a, float b) {
    __half2 h = __floats2half2_rn(a, b);   // a -> low half
    return *(uint32_t*)&h;
}

#define CP_ASYNC16(smem_u32_, gptr) \
    asm volatile("cp.async.cg.shared.global [%0], [%1], 16;" \
                 :: "r"(smem_u32_), "l"(gptr) : "memory")
#define CP_ASYNC_COMMIT() asm volatile("cp.async.commit_group;" ::: "memory")

__device__ __forceinline__ uint32_t smem_u32(const void* p) {
    uint32_t a;
    asm("{ .reg .u64 t; cvta.to.shared.u64 t, %1; cvt.u32.u64 %0, t; }"
        : "=r"(a) : "l"(p));
    return a;
}

// ---------------------------------------------------------------------------
// Kernel 0: W transpose + fp16x2 pack (once, tiny).
// ---------------------------------------------------------------------------
__global__ __launch_bounds__(256) void wconv_kernel(
    const float* __restrict__ Wk,
    const float* __restrict__ Wq,
    const float* __restrict__ Wv)
{
    int idx = blockIdx.x * 256 + threadIdx.x;   // 0..98303
    int n  = idx >> 9;                          // 0..191
    int k2 = idx & 511;
    int s = n >> 6, nn = n & 63;
    const float* W = (s == 0) ? Wk : ((s == 1) ? Wq : Wv);
    g_wt16[idx] = pack_h2(W[(2 * k2) * H_ + nn], W[(2 * k2 + 1) * H_ + nn]);
}

// ---------------------------------------------------------------------------
// Kernel 1: FUSED QKV projection, single-pass fp16 m16n8k16,
// cp.async double-buffered pipeline.
// Block: 128 threads (4 warps). M-tile 64, N = 192, K chunks of 32.
// x staged RAW fp32 (cp.async, no reg round-trip); fp32->fp16 conversion
// happens at A-fragment build (8 LDS.64 + 8 cvt per chunk per thread).
// W staged pre-packed fp16 via cp.async.
// x stage stride 36 floats (2-way LDS conflicts max, 16B-aligned rows);
// w stage stride 20 words (frag reads fully conflict-free, proven R14/15).
// ---------------------------------------------------------------------------
#define XSF 36                               // floats per x-stage row
#define WTW 20                               // words per w-stage row
#define XS_BYTES (64 * XSF * 4)              // 9216
#define WT_BYTES (192 * WTW * 4)             // 15360
#define STAGE_BYTES (XS_BYTES + WT_BYTES)    // 24576
#define PROJ_SMEM (2 * STAGE_BYTES)          // 49152

__device__ __forceinline__ void proj_issue(const float* __restrict__ x,
                                           long rowBase, int ch,
                                           uint32_t xs_s, uint32_t wt_s, int tid)
{
    const int k0 = ch * 32;
    // x: 64 rows x 128B = 512 x 16B; 4 per thread
    #pragma unroll
    for (int i = 0; i < 4; i++) {
        int idx = tid + i * 128;
        int r = idx >> 3, c16 = idx & 7;
        CP_ASYNC16(xs_s + (uint32_t)(r * (XSF * 4) + c16 * 16),
                   &x[(rowBase + r) * E_ + k0 + c16 * 4]);
    }
    // W: 192 rows x 64B = 768 x 16B; 6 per thread
    #pragma unroll
    for (int i = 0; i < 6; i++) {
        int idx = tid + i * 128;
        int n = idx >> 2, q = idx & 3;
        CP_ASYNC16(wt_s + (uint32_t)(n * (WTW * 4) + q * 16),
                   &g_wt16[n * 512 + ch * 16 + q * 4]);
    }
}

__global__ __launch_bounds__(128) void proj_kernel(const float* __restrict__ x)
{
    extern __shared__ char psm[];
    const int tid  = threadIdx.x;
    const int w    = tid >> 5;
    const int lane = tid & 31;
    const int g    = lane >> 2;
    const int t    = lane & 3;
    const long rowBase = (long)blockIdx.x * 64;
    const uint32_t sbase = smem_u32(psm);

    const uint32_t xs_s[2] = { sbase, sbase + STAGE_BYTES };
    const uint32_t wt_s[2] = { sbase + XS_BYTES, sbase + STAGE_BYTES + XS_BYTES };

    float acc[24][4] = {};

    proj_issue(x, rowBase, 0, xs_s[0], wt_s[0], tid);
    CP_ASYNC_COMMIT();

    for (int ch = 0; ch < 32; ch++) {
        const int cur = ch & 1;
        __syncthreads();   // all warps done reading buf[cur^1] (prev MMA)
        if (ch + 1 < 32) {
            proj_issue(x, rowBase, ch + 1, xs_s[cur ^ 1], wt_s[cur ^ 1], tid);
            CP_ASYNC_COMMIT();
            asm volatile("cp.async.wait_group 1;" ::: "memory");  // chunk ch done
        } else {
            asm volatile("cp.async.wait_group 0;" ::: "memory");
        }
        __syncthreads();   // staged data visible to all warps

        const float*    xs = (const float*)(psm + cur * STAGE_BYTES);
        const uint32_t* wt = (const uint32_t*)(psm + cur * STAGE_BYTES + XS_BYTES);

        #pragma unroll
        for (int ks = 0; ks < 2; ks++) {
            const int kk = ks * 8;
            const int r0 = w * 16 + g;
            // A fragments: fp32 pairs from smem -> fp16x2 (conversion here)
            float2 f0 = *(const float2*)&xs[(r0    ) * XSF + 2 * (kk + t)];
            float2 f1 = *(const float2*)&xs[(r0 + 8) * XSF + 2 * (kk + t)];
            float2 f2 = *(const float2*)&xs[(r0    ) * XSF + 2 * (kk + t + 4)];
            float2 f3 = *(const float2*)&xs[(r0 + 8) * XSF + 2 * (kk + t + 4)];
            uint32_t a0 = pack_h2(f0.x, f0.y);
            uint32_t a1 = pack_h2(f1.x, f1.y);
            uint32_t a2 = pack_h2(f2.x, f2.y);
            uint32_t a3 = pack_h2(f3.x, f3.y);
            #pragma unroll
            for (int nt = 0; nt < 24; nt++) {
                uint32_t b0 = wt[(nt * 8 + g) * WTW + kk + t];
                uint32_t b1 = wt[(nt * 8 + g) * WTW + kk + t + 4];
                mma_fp16(acc[nt], a0, a1, a2, a3, b0, b1);
            }
        }
    }

    // store fp16x2 packed along d: word (row)*32 + (nt&7)*4 + t
    const long r0g = rowBase + w * 16 + g;
    #pragma unroll
    for (int nt = 0; nt < 24; nt++) {
        uint32_t* o = (nt < 8) ? g_k16 : ((nt < 16) ? g_q16 : g_v16);
        int wd = (nt & 7) * 4 + t;
        o[(r0g    ) * 32 + wd] = pack_h2(acc[nt][0], acc[nt][1]);
        o[(r0g + 8) * 32 + wd] = pack_h2(acc[nt][2], acc[nt][3]);
    }
}

// ---------------------------------------------------------------------------
// Kernel 1b: V transpose. g_v16 [b*T+s][d/2] -> g_vt16 [b][d][s/2].
// One block per (b, 64-row s-tile). smem-tiled, coalesced both sides.
// ---------------------------------------------------------------------------
__global__ __launch_bounds__(256) void vtrans_kernel()
{
    __shared__ __half sm[64][80];   // [d][s], row stride 160 B (16B aligned)
    const int st = blockIdx.x;      // s-tile 0..31
    const int b  = blockIdx.y;
    const int tid = threadIdx.x;

    #pragma unroll
    for (int i = 0; i < 8; i++) {
        int idx = tid + i * 256;
        int s = idx >> 5, wd = idx & 31;
        uint32_t v = g_v16[((long)b * T_ + st * 64 + s) * 32 + wd];
        __half2 h = *(__half2*)&v;
        sm[2 * wd    ][s] = __low2half(h);
        sm[2 * wd + 1][s] = __high2half(h);
    }
    __syncthreads();

    #pragma unroll
    for (int i = 0; i < 8; i++) {
        int idx = tid + i * 256;
        int d = idx >> 5, q = idx & 31;
        uint32_t v = *(uint32_t*)&sm[d][2 * q];
        g_vt16[((size_t)b * 64 + d) * 1024 + st * 32 + q] = v;
    }
}

// ---------------------------------------------------------------------------
// Kernel 2: causal flash attention, fp16 m16n8k16 (R15 version, measured 72us).
// Block: 128 threads (4 warps). Q-tile 64 x K-tile 64.
// smem stride 36 words; all operands pre-packed fp16x2.
// ---------------------------------------------------------------------------
#define AS 36
#define ATTN_SMEM (4 * 64 * AS * 4)   // 36864 B

__global__ __launch_bounds__(128) void attn_kernel(float* __restrict__ out)
{
    extern __shared__ uint32_t asm_[];
    uint32_t* qs  = asm_;
    uint32_t* ks  = qs  + 64 * AS;
    uint32_t* vts = ks  + 64 * AS;
    uint32_t* ps  = vts + 64 * AS;

    const int qi = blockIdx.x;     // query tile 0..31
    const int b  = blockIdx.y;     // batch
    const int tid  = threadIdx.x;
    const int w    = tid >> 5;
    const int lane = tid & 31;
    const int g    = lane >> 2;
    const int t    = lane & 3;

    const uint32_t* qb  = g_q16 + ((long)b * T_ + (long)qi * 64) * 32;
    const uint32_t* kb  = g_k16 + (long)b * T_ * 32;
    const uint32_t* vtb = g_vt16 + (size_t)b * 64 * 1024;

    #pragma unroll
    for (int i = 0; i < 4; i++) {
        int idx = tid + i * 128;
        int r = idx >> 3, q4 = (idx & 7) * 4;
        *(uint4*)&qs[r * AS + q4] = *(const uint4*)&qb[r * 32 + q4];
    }

    float oc[8][4] = {};
    float m0 = -INFINITY, m1 = -INFINITY, l0 = 0.0f, l1 = 0.0f;
    const float scale = 0.125f;    // 64^-0.5

    const int r0s    = w * 16 + g;
    const int row_g0 = qi * 64 + r0s;
    const int row_g1 = row_g0 + 8;

    for (int j = 0; j <= qi; j++) {
        __syncthreads();
        #pragma unroll
        for (int i = 0; i < 4; i++) {
            int idx = tid + i * 128;
            int r = idx >> 3, q4 = (idx & 7) * 4;
            *(uint4*)&ks [r * AS + q4] = *(const uint4*)&kb [((long)j * 64 + r) * 32 + q4];
            *(uint4*)&vts[r * AS + q4] = *(const uint4*)&vtb[(size_t)r * 1024 + j * 32 + q4];
        }
        __syncthreads();

        // ---- S = Q K^T ----
        float sc[8][4];
        #pragma unroll
        for (int nt = 0; nt < 8; nt++)
            #pragma unroll
            for (int ci = 0; ci < 4; ci++) sc[nt][ci] = 0.0f;

        #pragma unroll
        for (int ks4 = 0; ks4 < 4; ks4++) {
            const int kk2 = ks4 * 8;
            uint32_t a0 = qs[(r0s    ) * AS + kk2 + t];
            uint32_t a1 = qs[(r0s + 8) * AS + kk2 + t];
            uint32_t a2 = qs[(r0s    ) * AS + kk2 + t + 4];
            uint32_t a3 = qs[(r0s + 8) * AS + kk2 + t + 4];
            #pragma unroll
            for (int nt = 0; nt < 8; nt++) {
                uint32_t b0 = ks[(nt * 8 + g) * AS + kk2 + t];
                uint32_t b1 = ks[(nt * 8 + g) * AS + kk2 + t + 4];
                mma_fp16(sc[nt], a0, a1, a2, a3, b0, b1);
            }
        }

        // scale + causal mask (diagonal tile only)
        if (j == qi) {
            #pragma unroll
            for (int nt = 0; nt < 8; nt++) {
                int c0 = j * 64 + nt * 8 + 2 * t;
                sc[nt][0] = (c0     > row_g0) ? -INFINITY : sc[nt][0] * scale;
                sc[nt][1] = (c0 + 1 > row_g0) ? -INFINITY : sc[nt][1] * scale;
                sc[nt][2] = (c0     > row_g1) ? -INFINITY : sc[nt][2] * scale;
                sc[nt][3] = (c0 + 1 > row_g1) ? -INFINITY : sc[nt][3] * scale;
            }
        } else {
            #pragma unroll
            for (int nt = 0; nt < 8; nt++)
                #pragma unroll
                for (int ci = 0; ci < 4; ci++) sc[nt][ci] *= scale;
        }

        // ---- online softmax ----
        float mx0 = -INFINITY, mx1 = -INFINITY;
        #pragma unroll
        for (int nt = 0; nt < 8; nt++) {
            mx0 = fmaxf(mx0, fmaxf(sc[nt][0], sc[nt][1]));
            mx1 = fmaxf(mx1, fmaxf(sc[nt][2], sc[nt][3]));
        }
        #pragma unroll
        for (int off = 1; off < 4; off <<= 1) {
            mx0 = fmaxf(mx0, __shfl_xor_sync(0xffffffffu, mx0, off));
            mx1 = fmaxf(mx1, __shfl_xor_sync(0xffffffffu, mx1, off));
        }
        float mn0 = fmaxf(m0, mx0), mn1 = fmaxf(m1, mx1);
        float al0 = __expf(m0 - mn0), al1 = __expf(m1 - mn1);
        m0 = mn0; m1 = mn1;

        float rs0 = 0.0f, rs1 = 0.0f;
        #pragma unroll
        for (int nt = 0; nt < 8; nt++) {
            sc[nt][0] = __expf(sc[nt][0] - mn0);
            sc[nt][1] = __expf(sc[nt][1] - mn0);
            sc[nt][2] = __expf(sc[nt][2] - mn1);
            sc[nt][3] = __expf(sc[nt][3] - mn1);
            rs0 += sc[nt][0] + sc[nt][1];
            rs1 += sc[nt][2] + sc[nt][3];
        }
        #pragma unroll
        for (int off = 1; off < 4; off <<= 1) {
            rs0 += __shfl_xor_sync(0xffffffffu, rs0, off);
            rs1 += __shfl_xor_sync(0xffffffffu, rs1, off);
        }
        l0 = l0 * al0 + rs0;
        l1 = l1 * al1 + rs1;

        // rescale O, stage P (fp16x2 packed along s)
        #pragma unroll
        for (int nt = 0; nt < 8; nt++) {
            oc[nt][0] *= al0; oc[nt][1] *= al0;
            oc[nt][2] *= al1; oc[nt][3] *= al1;
            int wd = nt * 4 + t;
            ps[(r0s    ) * AS + wd] = pack_h2(sc[nt][0], sc[nt][1]);
            ps[(r0s + 8) * AS + wd] = pack_h2(sc[nt][2], sc[nt][3]);
        }
        __syncwarp();

        // ---- O += P V ----
        #pragma unroll
        for (int ks4 = 0; ks4 < 4; ks4++) {
            const int kk2 = ks4 * 8;
            uint32_t a0 = ps[(r0s    ) * AS + kk2 + t];
            uint32_t a1 = ps[(r0s + 8) * AS + kk2 + t];
            uint32_t a2 = ps[(r0s    ) * AS + kk2 + t + 4];
            uint32_t a3 = ps[(r0s + 8) * AS + kk2 + t + 4];
            #pragma unroll
            for (int nt = 0; nt < 8; nt++) {
                uint32_t b0 = vts[(nt * 8 + g) * AS + kk2 + t];
                uint32_t b1 = vts[(nt * 8 + g) * AS + kk2 + t + 4];
                mma_fp16(oc[nt], a0, a1, a2, a3, b0, b1);
            }
        }
    }

    // normalize + write out (fp32)
    float inv0 = 1.0f / l0, inv1 = 1.0f / l1;
    float* ob = out + ((long)b * T_) * H_;
    #pragma unroll
    for (int nt = 0; nt < 8; nt++) {
        int c = nt * 8 + 2 * t;
        *(float2*)&ob[(long)row_g0 * H_ + c] =
            make_float2(oc[nt][0] * inv0, oc[nt][1] * inv0);
        *(float2*)&ob[(long)row_g1 * H_ + c] =
            make_float2(oc[nt][2] * inv1, oc[nt][3] * inv1);
    }
}

// ---------------------------------------------------------------------------
extern "C" void kernel_launch(void* const* d_in, const int* in_sizes, int n_in,
                              void* d_out, int out_size)
{
    const float* x  = (const float*)d_in[0];
    const float* Wk = (const float*)d_in[1];
    const float* Wq = (const float*)d_in[2];
    const float* Wv = (const float*)d_in[3];
    float* out = (float*)d_out;

    cudaFuncSetAttribute(proj_kernel, cudaFuncAttributeMaxDynamicSharedMemorySize,
                         PROJ_SMEM);
    cudaFuncSetAttribute(attn_kernel, cudaFuncAttributeMaxDynamicSharedMemorySize,
                         ATTN_SMEM);

    // W transpose + fp16 pack
    wconv_kernel<<<384, 256>>>(Wk, Wq, Wv);

    // Fused QKV projection: 512 M-tiles of 64 rows
    proj_kernel<<<512, 128, PROJ_SMEM>>>(x);

    // V transpose: (32 s-tiles, 16 batches)
    vtrans_kernel<<<dim3(32, B_), 256>>>();

    // Flash attention: (32 q-tiles, 16 batches)
    attn_kernel<<<dim3(T_ / 64, B_), 128, ATTN_SMEM>>>(out);
}

// round 17
// speedup vs baseline: 4.0415x; 1.1206x over previous
#include <cuda_runtime.h>
#include <cuda_bf16.h>
#include <cuda_fp16.h>
#include <math.h>
#include <stdint.h>

// Problem constants
#define B_   16
#define T_   2048
#define E_   1024
#define H_   64

// Scratch (device globals: no allocation allowed)
// q,k,v stored as fp16x2 packed along head-dim d: [b*T + s][d/2] (32 words/row)
// NOTE: g_q16 is PRE-SCALED by 0.125 (softmax scale folded in).
__device__ uint32_t g_q16[B_ * T_ * 32];
__device__ uint32_t g_k16[B_ * T_ * 32];
__device__ uint32_t g_v16[B_ * T_ * 32];
// v transposed per batch: [b][d][s/2] packed along s (1024 words per d-row)
__device__ uint32_t g_vt16[(size_t)B_ * 64 * 1024];
// Pre-transposed fp16x2-packed weights: g_wt16[n*512 + k2]
__device__ uint32_t g_wt16[192 * 512];

// ---------------------------------------------------------------------------
// helpers
// ---------------------------------------------------------------------------
__device__ __forceinline__ void mma_fp16(float c[4],
                                         uint32_t a0, uint32_t a1, uint32_t a2, uint32_t a3,
                                         uint32_t b0, uint32_t b1)
{
    asm volatile(
        "mma.sync.aligned.m16n8k16.row.col.f32.f16.f16.f32 "
        "{%0,%1,%2,%3}, {%4,%5,%6,%7}, {%8,%9}, {%0,%1,%2,%3};\n"
        : "+f"(c[0]), "+f"(c[1]), "+f"(c[2]), "+f"(c[3])
        : "r"(a0), "r"(a1), "r"(a2), "r"(a3), "r"(b0), "r"(b1));
}

__device__ __forceinline__ void ldsm_x4(uint32_t& r0, uint32_t& r1,
                                        uint32_t& r2, uint32_t& r3, uint32_t addr)
{
    asm volatile("ldmatrix.sync.aligned.m8n8.x4.shared.b16 {%0,%1,%2,%3}, [%4];"
                 : "=r"(r0), "=r"(r1), "=r"(r2), "=r"(r3) : "r"(addr));
}

__device__ __forceinline__ uint32_t pack_h2(float a, float b) {
    __half2 h = __floats2half2_rn(a, b);   // a -> low half
    return *(uint32_t*)&h;
}

#define CP_ASYNC16(smem_u32_, gptr) \
    asm volatile("cp.async.cg.shared.global [%0], [%1], 16;" \
                 :: "r"(smem_u32_), "l"(gptr) : "memory")
#define CP_ASYNC_COMMIT() asm volatile("cp.async.commit_group;" ::: "memory")

__device__ __forceinline__ uint32_t smem_u32(const void* p) {
    uint32_t a;
    asm("{ .reg .u64 t; cvta.to.shared.u64 t, %1; cvt.u32.u64 %0, t; }"
        : "=r"(a) : "l"(p));
    return a;
}

// ---------------------------------------------------------------------------
// Kernel 0: W transpose + fp16x2 pack (once, tiny).
// ---------------------------------------------------------------------------
__global__ __launch_bounds__(256) void wconv_kernel(
    const float* __restrict__ Wk,
    const float* __restrict__ Wq,
    const float* __restrict__ Wv)
{
    int idx = blockIdx.x * 256 + threadIdx.x;   // 0..98303
    int n  = idx >> 9;                          // 0..191
    int k2 = idx & 511;
    int s = n >> 6, nn = n & 63;
    const float* W = (s == 0) ? Wk : ((s == 1) ? Wq : Wv);
    g_wt16[idx] = pack_h2(W[(2 * k2) * H_ + nn], W[(2 * k2 + 1) * H_ + nn]);
}

// ---------------------------------------------------------------------------
// Kernel 1: FUSED QKV projection, single-pass fp16 m16n8k16,
// cp.async double-buffered pipeline (R16 structure, measured) + ldmatrix
// for W b-fragments + q pre-scaled by 0.125 at store.
// Block: 128 threads (4 warps). M-tile 64, N = 192, K chunks of 32.
// ---------------------------------------------------------------------------
#define XSF 36                               // floats per x-stage row
#define WTW 20                               // words per w-stage row (80 B)
#define XS_BYTES (64 * XSF * 4)              // 9216
#define WT_BYTES (192 * WTW * 4)             // 15360
#define STAGE_BYTES (XS_BYTES + WT_BYTES)    // 24576
#define PROJ_SMEM (2 * STAGE_BYTES)          // 49152

__device__ __forceinline__ void proj_issue(const float* __restrict__ x,
                                           long rowBase, int ch,
                                           uint32_t xs_s, uint32_t wt_s, int tid)
{
    const int k0 = ch * 32;
    #pragma unroll
    for (int i = 0; i < 4; i++) {
        int idx = tid + i * 128;
        int r = idx >> 3, c16 = idx & 7;
        CP_ASYNC16(xs_s + (uint32_t)(r * (XSF * 4) + c16 * 16),
                   &x[(rowBase + r) * E_ + k0 + c16 * 4]);
    }
    #pragma unroll
    for (int i = 0; i < 6; i++) {
        int idx = tid + i * 128;
        int n = idx >> 2, q = idx & 3;
        CP_ASYNC16(wt_s + (uint32_t)(n * (WTW * 4) + q * 16),
                   &g_wt16[n * 512 + ch * 16 + q * 4]);
    }
}

__global__ __launch_bounds__(128) void proj_kernel(const float* __restrict__ x)
{
    extern __shared__ char psm[];
    const int tid  = threadIdx.x;
    const int w    = tid >> 5;
    const int lane = tid & 31;
    const int g    = lane >> 2;
    const int t    = lane & 3;
    const int lm   = lane >> 3;    // ldmatrix matrix index 0..3
    const int lr   = lane & 7;     // ldmatrix row within matrix
    const long rowBase = (long)blockIdx.x * 64;
    const uint32_t sbase = smem_u32(psm);

    const uint32_t xs_s[2] = { sbase, sbase + STAGE_BYTES };
    const uint32_t wt_s[2] = { sbase + XS_BYTES, sbase + STAGE_BYTES + XS_BYTES };

    // per-lane ldmatrix const for W b-frags (stride 80 B):
    // m0: b0 nt-even, m1: b1 nt-even, m2: b0 nt-odd, m3: b1 nt-odd
    const uint32_t wconst = (uint32_t)((lm >> 1) * (8 * 80) + lr * 80 + (lm & 1) * 16);

    float acc[24][4] = {};

    proj_issue(x, rowBase, 0, xs_s[0], wt_s[0], tid);
    CP_ASYNC_COMMIT();

    for (int ch = 0; ch < 32; ch++) {
        const int cur = ch & 1;
        __syncthreads();
        if (ch + 1 < 32) {
            proj_issue(x, rowBase, ch + 1, xs_s[cur ^ 1], wt_s[cur ^ 1], tid);
            CP_ASYNC_COMMIT();
            asm volatile("cp.async.wait_group 1;" ::: "memory");
        } else {
            asm volatile("cp.async.wait_group 0;" ::: "memory");
        }
        __syncthreads();

        const float* xs = (const float*)(psm + cur * STAGE_BYTES);
        const uint32_t wtb = wt_s[cur];

        #pragma unroll
        for (int ks = 0; ks < 2; ks++) {
            const int kk = ks * 8;
            const int r0 = w * 16 + g;
            float2 f0 = *(const float2*)&xs[(r0    ) * XSF + 2 * (kk + t)];
            float2 f1 = *(const float2*)&xs[(r0 + 8) * XSF + 2 * (kk + t)];
            float2 f2 = *(const float2*)&xs[(r0    ) * XSF + 2 * (kk + t + 4)];
            float2 f3 = *(const float2*)&xs[(r0 + 8) * XSF + 2 * (kk + t + 4)];
            uint32_t a0 = pack_h2(f0.x, f0.y);
            uint32_t a1 = pack_h2(f1.x, f1.y);
            uint32_t a2 = pack_h2(f2.x, f2.y);
            uint32_t a3 = pack_h2(f3.x, f3.y);
            #pragma unroll
            for (int ntp = 0; ntp < 12; ntp++) {
                uint32_t b0e, b1e, b0o, b1o;
                ldsm_x4(b0e, b1e, b0o, b1o,
                        wtb + wconst + (uint32_t)(ntp * (16 * 80) + ks * 32));
                mma_fp16(acc[2 * ntp    ], a0, a1, a2, a3, b0e, b1e);
                mma_fp16(acc[2 * ntp + 1], a0, a1, a2, a3, b0o, b1o);
            }
        }
    }

    // store fp16x2 packed along d; q (nt 8..15) pre-scaled by 0.125
    const long r0g = rowBase + w * 16 + g;
    #pragma unroll
    for (int nt = 0; nt < 24; nt++) {
        uint32_t* o = (nt < 8) ? g_k16 : ((nt < 16) ? g_q16 : g_v16);
        const float s = (nt >= 8 && nt < 16) ? 0.125f : 1.0f;
        int wd = (nt & 7) * 4 + t;
        o[(r0g    ) * 32 + wd] = pack_h2(acc[nt][0] * s, acc[nt][1] * s);
        o[(r0g + 8) * 32 + wd] = pack_h2(acc[nt][2] * s, acc[nt][3] * s);
    }
}

// ---------------------------------------------------------------------------
// Kernel 1b: V transpose. g_v16 [b*T+s][d/2] -> g_vt16 [b][d][s/2].
// ---------------------------------------------------------------------------
__global__ __launch_bounds__(256) void vtrans_kernel()
{
    __shared__ __half sm[64][80];
    const int st = blockIdx.x;      // s-tile 0..31
    const int b  = blockIdx.y;
    const int tid = threadIdx.x;

    #pragma unroll
    for (int i = 0; i < 8; i++) {
        int idx = tid + i * 256;
        int s = idx >> 5, wd = idx & 31;
        uint32_t v = g_v16[((long)b * T_ + st * 64 + s) * 32 + wd];
        __half2 h = *(__half2*)&v;
        sm[2 * wd    ][s] = __low2half(h);
        sm[2 * wd + 1][s] = __high2half(h);
    }
    __syncthreads();

    #pragma unroll
    for (int i = 0; i < 8; i++) {
        int idx = tid + i * 256;
        int d = idx >> 5, q = idx & 31;
        uint32_t v = *(uint32_t*)&sm[d][2 * q];
        g_vt16[((size_t)b * 64 + d) * 1024 + st * 32 + q] = v;
    }
}

// ---------------------------------------------------------------------------
// Kernel 2: causal flash attention, fp16 m16n8k16, ldmatrix fragments,
// cp.async double-buffered K/V.
// Block: 128 threads (4 warps). Q-tile 64 x K-tile 64.
// smem: qs[64x36], ps[64x36], {ks,vts} x 2 stages -> 55296 B.
// Row stride 144 B; ldmatrix phases cover all 32 banks (4r start pattern).
// q is pre-scaled by 0.125 (no scale multiply in the loop).
// ---------------------------------------------------------------------------
#define AS 36
#define TILE_B (64 * AS * 4)            // 9216 B per array
#define ATTN_SMEM (6 * TILE_B)          // 55296 B

__global__ __launch_bounds__(128) void attn_kernel(float* __restrict__ out)
{
    extern __shared__ uint32_t asm_[];
    const int qi = blockIdx.x;     // query tile 0..31
    const int b  = blockIdx.y;     // batch
    const int tid  = threadIdx.x;
    const int w    = tid >> 5;
    const int lane = tid & 31;
    const int t    = lane & 3;
    const int lm   = lane >> 3;
    const int lr   = lane & 7;

    const uint32_t abase = smem_u32(asm_);
    const uint32_t qs_b  = abase;                 // qs
    const uint32_t ps_b  = abase + TILE_B;        // ps
    // stages: [ks0,vts0] at abase+2*TILE_B, [ks1,vts1] at +4*TILE_B
    uint32_t* qs = asm_;

    const uint32_t* qb  = g_q16 + ((long)b * T_ + (long)qi * 64) * 32;
    const uint32_t* kb  = g_k16 + (long)b * T_ * 32;
    const uint32_t* vtb = g_vt16 + (size_t)b * 64 * 1024;

    // ldmatrix per-lane address constants (stride 144 B)
    // a-frags (qs/ps): m0:a0, m1:a1(+8 rows), m2:a2(+4 words), m3:a3
    const uint32_t aconst = (uint32_t)((w * 16 + (lm & 1) * 8 + lr) * 144 + (lm >> 1) * 16);
    // b-frags (ks/vts): m0:b0 nt-even, m1:b1 nt-even, m2:b0 nt-odd, m3:b1 nt-odd
    const uint32_t bconst = (uint32_t)((lm >> 1) * (8 * 144) + lr * 144 + (lm & 1) * 16);

    // load Q tile (plain; stride-36 rows, 16B aligned)
    #pragma unroll
    for (int i = 0; i < 4; i++) {
        int idx = tid + i * 128;
        int r = idx >> 3, q4 = (idx & 7) * 4;
        *(uint4*)&qs[r * AS + q4] = *(const uint4*)&qb[r * 32 + q4];
    }

    // prologue: issue tile j=0 into stage 0
    {
        const uint32_t ks_s = abase + 2 * TILE_B;
        const uint32_t vt_s = ks_s + TILE_B;
        #pragma unroll
        for (int i = 0; i < 4; i++) {
            int idx = tid + i * 128;
            int r = idx >> 3, c16 = idx & 7;
            CP_ASYNC16(ks_s + (uint32_t)(r * 144 + c16 * 16), &kb [(long)r * 32 + c16 * 4]);
            CP_ASYNC16(vt_s + (uint32_t)(r * 144 + c16 * 16), &vtb[(size_t)r * 1024 + c16 * 4]);
        }
        CP_ASYNC_COMMIT();
    }

    float oc[8][4] = {};
    float m0 = -INFINITY, m1 = -INFINITY, l0 = 0.0f, l1 = 0.0f;

    const int r0s    = w * 16 + (lane >> 2);
    const int row_g0 = qi * 64 + r0s;
    const int row_g1 = row_g0 + 8;

    for (int j = 0; j <= qi; j++) {
        const int cur = j & 1;
        __syncthreads();   // prev iteration done reading stage cur^1
        if (j + 1 <= qi) {
            const uint32_t ks_s = abase + (2 + 2 * (cur ^ 1)) * TILE_B;
            const uint32_t vt_s = ks_s + TILE_B;
            #pragma unroll
            for (int i = 0; i < 4; i++) {
                int idx = tid + i * 128;
                int r = idx >> 3, c16 = idx & 7;
                CP_ASYNC16(ks_s + (uint32_t)(r * 144 + c16 * 16),
                           &kb[((long)(j + 1) * 64 + r) * 32 + c16 * 4]);
                CP_ASYNC16(vt_s + (uint32_t)(r * 144 + c16 * 16),
                           &vtb[(size_t)r * 1024 + (j + 1) * 32 + c16 * 4]);
            }
            CP_ASYNC_COMMIT();
            asm volatile("cp.async.wait_group 1;" ::: "memory");
        } else {
            asm volatile("cp.async.wait_group 0;" ::: "memory");
        }
        __syncthreads();

        const uint32_t kbb = abase + (2 + 2 * cur) * TILE_B;
        const uint32_t vbb = kbb + TILE_B;

        // ---- S = Q K^T ----
        float sc[8][4];
        #pragma unroll
        for (int nt = 0; nt < 8; nt++)
            #pragma unroll
            for (int ci = 0; ci < 4; ci++) sc[nt][ci] = 0.0f;

        #pragma unroll
        for (int ks4 = 0; ks4 < 4; ks4++) {
            uint32_t a0, a1, a2, a3;
            ldsm_x4(a0, a1, a2, a3, qs_b + aconst + (uint32_t)(ks4 * 32));
            #pragma unroll
            for (int ntp = 0; ntp < 4; ntp++) {
                uint32_t b0e, b1e, b0o, b1o;
                ldsm_x4(b0e, b1e, b0o, b1o,
                        kbb + bconst + (uint32_t)(ntp * (16 * 144) + ks4 * 32));
                mma_fp16(sc[2 * ntp    ], a0, a1, a2, a3, b0e, b1e);
                mma_fp16(sc[2 * ntp + 1], a0, a1, a2, a3, b0o, b1o);
            }
        }

        // causal mask (diagonal tile only; q pre-scaled, no scale here)
        if (j == qi) {
            #pragma unroll
            for (int nt = 0; nt < 8; nt++) {
                int c0 = j * 64 + nt * 8 + 2 * t;
                if (c0     > row_g0) sc[nt][0] = -INFINITY;
                if (c0 + 1 > row_g0) sc[nt][1] = -INFINITY;
                if (c0     > row_g1) sc[nt][2] = -INFINITY;
                if (c0 + 1 > row_g1) sc[nt][3] = -INFINITY;
            }
        }

        // ---- online softmax ----
        float mx0 = -INFINITY, mx1 = -INFINITY;
        #pragma unroll
        for (int nt = 0; nt < 8; nt++) {
            mx0 = fmaxf(mx0, fmaxf(sc[nt][0], sc[nt][1]));
            mx1 = fmaxf(mx1, fmaxf(sc[nt][2], sc[nt][3]));
        }
        #pragma unroll
        for (int off = 1; off < 4; off <<= 1) {
            mx0 = fmaxf(mx0, __shfl_xor_sync(0xffffffffu, mx0, off));
            mx1 = fmaxf(mx1, __shfl_xor_sync(0xffffffffu, mx1, off));
        }
        float mn0 = fmaxf(m0, mx0), mn1 = fmaxf(m1, mx1);
        float al0 = __expf(m0 - mn0), al1 = __expf(m1 - mn1);
        m0 = mn0; m1 = mn1;

        float rs0 = 0.0f, rs1 = 0.0f;
        #pragma unroll
        for (int nt = 0; nt < 8; nt++) {
            sc[nt][0] = __expf(sc[nt][0] - mn0);
            sc[nt][1] = __expf(sc[nt][1] - mn0);
            sc[nt][2] = __expf(sc[nt][2] - mn1);
            sc[nt][3] = __expf(sc[nt][3] - mn1);
            rs0 += sc[nt][0] + sc[nt][1];
            rs1 += sc[nt][2] + sc[nt][3];
        }
        #pragma unroll
        for (int off = 1; off < 4; off <<= 1) {
            rs0 += __shfl_xor_sync(0xffffffffu, rs0, off);
            rs1 += __shfl_xor_sync(0xffffffffu, rs1, off);
        }
        l0 = l0 * al0 + rs0;
        l1 = l1 * al1 + rs1;

        // rescale O, stage P (fp16x2 packed along s)
        uint32_t* ps = (uint32_t*)(asm_ + 64 * AS);
        #pragma unroll
        for (int nt = 0; nt < 8; nt++) {
            oc[nt][0] *= al0; oc[nt][1] *= al0;
            oc[nt][2] *= al1; oc[nt][3] *= al1;
            int wd = nt * 4 + t;
            ps[(r0s    ) * AS + wd] = pack_h2(sc[nt][0], sc[nt][1]);
            ps[(r0s + 8) * AS + wd] = pack_h2(sc[nt][2], sc[nt][3]);
        }
        __syncwarp();

        // ---- O += P V ----
        #pragma unroll
        for (int ks4 = 0; ks4 < 4; ks4++) {
            uint32_t a0, a1, a2, a3;
            ldsm_x4(a0, a1, a2, a3, ps_b + aconst + (uint32_t)(ks4 * 32));
            #pragma unroll
            for (int ntp = 0; ntp < 4; ntp++) {
                uint32_t b0e, b1e, b0o, b1o;
                ldsm_x4(b0e, b1e, b0o, b1o,
                        vbb + bconst + (uint32_t)(ntp * (16 * 144) + ks4 * 32));
                mma_fp16(oc[2 * ntp    ], a0, a1, a2, a3, b0e, b1e);
                mma_fp16(oc[2 * ntp + 1], a0, a1, a2, a3, b0o, b1o);
            }
        }
    }

    // normalize + write out (fp32)
    float inv0 = 1.0f / l0, inv1 = 1.0f / l1;
    float* ob = out + ((long)b * T_) * H_;
    #pragma unroll
    for (int nt = 0; nt < 8; nt++) {
        int c = nt * 8 + 2 * t;
        *(float2*)&ob[(long)row_g0 * H_ + c] =
            make_float2(oc[nt][0] * inv0, oc[nt][1] * inv0);
        *(float2*)&ob[(long)row_g1 * H_ + c] =
            make_float2(oc[nt][2] * inv1, oc[nt][3] * inv1);
    }
}

// ---------------------------------------------------------------------------
extern "C" void kernel_launch(void* const* d_in, const int* in_sizes, int n_in,
                              void* d_out, int out_size)
{
    const float* x  = (const float*)d_in[0];
    const float* Wk = (const float*)d_in[1];
    const float* Wq = (const float*)d_in[2];
    const float* Wv = (const float*)d_in[3];
    float* out = (float*)d_out;

    cudaFuncSetAttribute(proj_kernel, cudaFuncAttributeMaxDynamicSharedMemorySize,
                         PROJ_SMEM);
    cudaFuncSetAttribute(attn_kernel, cudaFuncAttributeMaxDynamicSharedMemorySize,
                         ATTN_SMEM);

    // W transpose + fp16 pack
    wconv_kernel<<<384, 256>>>(Wk, Wq, Wv);

    // Fused QKV projection: 512 M-tiles of 64 rows
    proj_kernel<<<512, 128, PROJ_SMEM>>>(x);

    // V transpose: (32 s-tiles, 16 batches)
    vtrans_kernel<<<dim3(32, B_), 256>>>();

    // Flash attention: (32 q-tiles, 16 batches)
    attn_kernel<<<dim3(T_ / 64, B_), 128, ATTN_SMEM>>>(out);
}